// round 12
// baseline (speedup 1.0000x reference)
#include <cuda_runtime.h>
#include <cuda_bf16.h>
#include <cstddef>
#include <cstdint>

#define SPI 9
#define BM  128

// Activations stored pre-split: per vertex [hi bf16 x C | lo bf16 x C].
__device__ __align__(16) __nv_bfloat16 g_bufX[(size_t)8 * 50000 * 128]; // L0 out (64B/row) / L2 out (256B/row)
__device__ __align__(16) __nv_bfloat16 g_bufY[(size_t)8 * 50000 * 64];  // L1 out (128B/row)
// Weights pre-shuffled into mma.sync B-fragment order.
__device__ __align__(16) uint4 g_WF1[9 * 1 * 2 * 2 * 32];
__device__ __align__(16) uint4 g_WF2[9 * 2 * 4 * 2 * 32];
__device__ __align__(16) uint4 g_WF3[9 * 4 * 8 * 2 * 32];

__device__ __forceinline__ void ffma2(float2 &d, const float2 &a, const float2 &b) {
    unsigned long long       &du = reinterpret_cast<unsigned long long &>(d);
    const unsigned long long &au = reinterpret_cast<const unsigned long long &>(a);
    const unsigned long long &bu = reinterpret_cast<const unsigned long long &>(b);
    asm("fma.rn.f32x2 %0, %1, %2, %0;" : "+l"(du) : "l"(au), "l"(bu));
}
__device__ __forceinline__ uint32_t smem_u32(const void *p) {
    uint32_t a;
    asm("{ .reg .u64 t; cvta.to.shared.u64 t, %1; cvt.u32.u64 %0, t; }" : "=r"(a) : "l"(p));
    return a;
}
#define SMEM_SWIZZLE_128B(o) ((o) ^ (((o) >> 3) & 0x70))

__device__ __forceinline__ void cp16(uint32_t dst, const void *src) {
    asm volatile("cp.async.cg.shared.global [%0], [%1], 16;" :: "r"(dst), "l"(src));
}
#define CP_COMMIT() asm volatile("cp.async.commit_group;" ::: "memory")
#define CP_WAIT0()  asm volatile("cp.async.wait_group 0;" ::: "memory")

__device__ __forceinline__ void ldmx4(uint32_t &r0, uint32_t &r1, uint32_t &r2,
                                      uint32_t &r3, uint32_t addr) {
    asm volatile("ldmatrix.sync.aligned.m8n8.x4.shared.b16 {%0,%1,%2,%3}, [%4];"
                 : "=r"(r0), "=r"(r1), "=r"(r2), "=r"(r3) : "r"(addr));
}
__device__ __forceinline__ void mma16816(float *c, const uint32_t *a,
                                         uint32_t b0, uint32_t b1) {
    asm volatile("mma.sync.aligned.m16n8k16.row.col.f32.bf16.bf16.f32 "
                 "{%0,%1,%2,%3}, {%4,%5,%6,%7}, {%8,%9}, {%0,%1,%2,%3};"
                 : "+f"(c[0]), "+f"(c[1]), "+f"(c[2]), "+f"(c[3])
                 : "r"(a[0]), "r"(a[1]), "r"(a[2]), "r"(a[3]), "r"(b0), "r"(b1));
}
__device__ __forceinline__ void split2(float2 v, uint32_t &h, uint32_t &l) {
    __nv_bfloat162 hb = __float22bfloat162_rn(v);
    float2 hf = __bfloat1622float2(hb);
    __nv_bfloat162 lb = __float22bfloat162_rn(make_float2(v.x - hf.x, v.y - hf.y));
    h = *(uint32_t *)&hb;
    l = *(uint32_t *)&lb;
}
__device__ __forceinline__ float2 recon2(uint32_t hw, uint32_t lw) {
    float2 hf = __bfloat1622float2(*(__nv_bfloat162 *)&hw);
    float2 lf = __bfloat1622float2(*(__nv_bfloat162 *)&lw);
    return make_float2(hf.x + lf.x, hf.y + lf.y);
}

// ---------------------------------------------------------------------------
// Layer 0 (FFMA2): Cin=3 -> 16, writes pre-split hi/lo rows (64B/vertex).
// ---------------------------------------------------------------------------
__global__ void layer0_kernel(const float *__restrict__ X, const int *__restrict__ idx,
                              const float *__restrict__ W, const float *__restrict__ bias,
                              __nv_bfloat16 *__restrict__ Y, int N) {
    __shared__ float Ws[27 * 16];
    __shared__ float bs[16];
    int tid = threadIdx.x;
    for (int t = tid; t < 27 * 16; t += blockDim.x) Ws[t] = W[t];
    if (tid < 16) bs[tid] = bias[tid];
    __syncthreads();

    int n = blockIdx.x * blockDim.x + tid;
    int b = blockIdx.y;
    if (n >= N) return;

    float2 acc[8];
#pragma unroll
    for (int j = 0; j < 8; j++) acc[j] = make_float2(bs[2 * j], bs[2 * j + 1]);

    const float *Xb = X + (size_t)b * N * 3;
#pragma unroll
    for (int s = 0; s < SPI; s++) {
        int r = idx[n * SPI + s];
        float xv[3];
        xv[0] = __ldg(Xb + (size_t)r * 3 + 0);
        xv[1] = __ldg(Xb + (size_t)r * 3 + 1);
        xv[2] = __ldg(Xb + (size_t)r * 3 + 2);
#pragma unroll
        for (int c = 0; c < 3; c++) {
            const float *wrow = Ws + (s * 3 + c) * 16;
            float2 vv = make_float2(xv[c], xv[c]);
#pragma unroll
            for (int j = 0; j < 8; j++) {
                float2 w = *(const float2 *)(wrow + 2 * j);
                ffma2(acc[j], vv, w);
            }
        }
    }
    uint32_t hi[8], lo[8];
#pragma unroll
    for (int j = 0; j < 8; j++) split2(acc[j], hi[j], lo[j]);
    char *y = (char *)Y + ((size_t)b * N + n) * 64;
    *(uint4 *)(y + 0)  = make_uint4(hi[0], hi[1], hi[2], hi[3]);
    *(uint4 *)(y + 16) = make_uint4(hi[4], hi[5], hi[6], hi[7]);
    *(uint4 *)(y + 32) = make_uint4(lo[0], lo[1], lo[2], lo[3]);
    *(uint4 *)(y + 48) = make_uint4(lo[4], lo[5], lo[6], lo[7]);
}

// ---------------------------------------------------------------------------
// Weight prep: W[S*CIN, COUT] -> mma B-fragment order, bf16 hi/lo.
// ---------------------------------------------------------------------------
template <int CIN, int COUT>
__global__ void prep_wfrag(const float *__restrict__ W, uint4 *__restrict__ dst) {
    constexpr int KCH = CIN / 16, NGT = COUT / 16;
    constexpr int PER = KCH * NGT * 64;
    int s = blockIdx.x;
    for (int i = threadIdx.x; i < PER; i += blockDim.x) {
        int lane = i & 31, h = (i >> 5) & 1, ngg = (i >> 6) % NGT, kc = (i >> 6) / NGT;
        int n0 = ngg * 16 + (lane >> 2);
        int kb = kc * 16 + 2 * (lane & 3);
        auto wsel = [&](int k, int n) -> uint32_t {
            float v = __ldg(W + (size_t)(s * CIN + k) * COUT + n);
            __nv_bfloat16 hb = __float2bfloat16_rn(v);
            if (h == 0) return (uint32_t)(*(uint16_t *)&hb);
            float r = v - __bfloat162float(hb);
            __nv_bfloat16 lb = __float2bfloat16_rn(r);
            return (uint32_t)(*(uint16_t *)&lb);
        };
        auto word = [&](int k, int n) { return wsel(k, n) | (wsel(k + 1, n) << 16); };
        uint4 q;
        q.x = word(kb,     n0);
        q.y = word(kb,     n0 + 8);
        q.z = word(kb + 8, n0);
        q.w = word(kb + 8, n0 + 8);
        dst[(size_t)s * PER + i] = q;
    }
}

// ---------------------------------------------------------------------------
// Layers 1-2: bf16x3 mma.sync (R10 structure, unchanged).
// ---------------------------------------------------------------------------
template <int CIN, int COUT>
__global__ void __launch_bounds__(256, 2)
layer_mma(const __nv_bfloat16 *__restrict__ X,
          const int   *__restrict__ idxg,
          const float *__restrict__ bias,
          const uint4 *__restrict__ WF,
          void *__restrict__ Y,
          int N) {
    constexpr int KCH = CIN / 16;
    constexpr int NGT = COUT / 16;
    constexpr int WN  = 1;
    constexpr int MT  = 1;
    constexpr int NG  = NGT;
    constexpr int CB  = 2 * CIN;
    constexpr int CPT = CB / 32;
    constexpr int XROW = 4 * CIN;
    constexpr int IDXOFF = 65536;
    constexpr int PRM = IDXOFF + 4608;

    extern __shared__ __align__(1024) char smc[];
    uint32_t sb = smem_u32(smc);
    int tid = threadIdx.x, wid = tid >> 5, lane = tid & 31;
    int b = blockIdx.y, row0 = blockIdx.x * BM;
    int warpM = wid;

    int *idxs = (int *)(smc + IDXOFF);
    for (int t = tid; t < SPI * BM; t += 256) {
        int m = t / SPI, s = t % SPI;
        int r = row0 + m;
        if (r >= N) r = N - 1;
        idxs[s * BM + m] = idxg[(size_t)r * SPI + s];
    }
    float *prm = (float *)(smc + PRM);
    if (tid < COUT) prm[tid] = bias[tid];

    float acc[MT][2 * NG][4];
#pragma unroll
    for (int mt = 0; mt < MT; mt++)
#pragma unroll
        for (int nf = 0; nf < 2 * NG; nf++)
#pragma unroll
            for (int c = 0; c < 4; c++) acc[mt][nf][c] = 0.0f;

    const char *Xb = (const char *)X + (size_t)b * N * XROW;
    int grow = tid >> 1, ghalf = tid & 1;
    uint32_t lm_row  = (uint32_t)(lane & 15);
    uint32_t lm_half = (uint32_t)(lane >> 4) << 4;

    __syncthreads();

    auto issueA = [&](int s, int st) {
        int r = idxs[s * BM + grow];
        const char *src = Xb + (size_t)r * XROW;
        uint32_t ah = sb + (uint32_t)st * 16384;
        uint32_t al = sb + 32768 + (uint32_t)st * 16384;
#pragma unroll
        for (int q = 0; q < CPT; q++) {
            int c = ghalf * CPT + q;
            uint32_t so = SMEM_SWIZZLE_128B((uint32_t)(grow * 128 + 16 * c));
            cp16(ah + so, src + 16 * c);
            cp16(al + so, src + CB + 16 * c);
        }
    };

    issueA(0, 0);
    CP_COMMIT();

    for (int s = 0; s < SPI; s++) {
        int st = s & 1;
        CP_WAIT0();
        __syncthreads();
        if (s + 1 < SPI) {
            issueA(s + 1, st ^ 1);
            CP_COMMIT();
        }
        uint32_t aH = sb + (uint32_t)st * 16384;
        uint32_t aL = sb + 32768 + (uint32_t)st * 16384;
#pragma unroll
        for (int kc = 0; kc < KCH; kc++) {
            uint32_t kcoff = (uint32_t)kc * 32 + lm_half;
            uint32_t Ah[4], Al[4];
            {
                uint32_t ro = (uint32_t)(warpM * 16 + lm_row) * 128 + kcoff;
                uint32_t so = SMEM_SWIZZLE_128B(ro);
                ldmx4(Ah[0], Ah[1], Ah[2], Ah[3], aH + so);
                ldmx4(Al[0], Al[1], Al[2], Al[3], aL + so);
            }
#pragma unroll
            for (int ng = 0; ng < NG; ng++) {
                const uint4 *bp = WF + ((((size_t)s * KCH + kc) * NGT + ng) * 2) * 32 + lane;
                uint4 qh = __ldg(bp);
                uint4 ql = __ldg(bp + 32);
                mma16816(acc[0][2 * ng],     Ah, qh.x, qh.z);
                mma16816(acc[0][2 * ng + 1], Ah, qh.y, qh.w);
                mma16816(acc[0][2 * ng],     Ah, ql.x, ql.z);
                mma16816(acc[0][2 * ng + 1], Ah, ql.y, ql.w);
                mma16816(acc[0][2 * ng],     Al, qh.x, qh.z);
                mma16816(acc[0][2 * ng + 1], Al, qh.y, qh.w);
            }
        }
    }

    char *Yb = (char *)Y + (size_t)b * N * (4 * COUT);
    {
        int rr = row0 + warpM * 16 + (lane >> 2);
#pragma unroll
        for (int nf = 0; nf < 2 * NG; nf++) {
            int c = nf * 8 + (lane & 3) * 2;
            float bv0 = prm[c], bv1 = prm[c + 1];
            uint32_t h, l;
            if (rr < N) {
                split2(make_float2(acc[0][nf][0] + bv0, acc[0][nf][1] + bv1), h, l);
                char *rp = Yb + (size_t)rr * (4 * COUT);
                *(uint32_t *)(rp + 2 * c) = h;
                *(uint32_t *)(rp + 2 * COUT + 2 * c) = l;
            }
            if (rr + 8 < N) {
                split2(make_float2(acc[0][nf][2] + bv0, acc[0][nf][3] + bv1), h, l);
                char *rp = Yb + (size_t)(rr + 8) * (4 * COUT);
                *(uint32_t *)(rp + 2 * c) = h;
                *(uint32_t *)(rp + 2 * COUT + 2 * c) = l;
            }
        }
    }
}

// ---------------------------------------------------------------------------
// Layer 3 HYBRID + fused final linear.
//   blocks [0, tmSplit):      tensor path (bf16x3 mma.sync, R10-identical)
//   blocks [tmSplit, tiles):  FFMA2 path on the fma pipe (R4-identical math,
//                             inputs reconstructed exactly as hi+lo)
// Both paths share idx (at 65536) and prm (at 70144) smem layouts.
// ---------------------------------------------------------------------------
#define IDXOFF3 65536
#define PRM3    (IDXOFF3 + 4608)
#define SMF3    (PRM3 + (384 + 4 + 128) * 4)
#define CSTR3   132

__global__ void __launch_bounds__(256, 2)
layer3_hybrid(const __nv_bfloat16 *__restrict__ X,   // split rows, 256B/vertex
              const int   *__restrict__ idxg,
              const float *__restrict__ b3,
              const uint4 *__restrict__ WF,          // mma fragments
              const float *__restrict__ W3,          // fp32 [576,128] (ffma path)
              const float *__restrict__ Wf,
              const float *__restrict__ bf,
              float *__restrict__ out,
              int N, int tmSplit) {
    extern __shared__ __align__(1024) char smc[];
    uint32_t sb = smem_u32(smc);
    int tid = threadIdx.x, wid = tid >> 5, lane = tid & 31;
    int b = blockIdx.y, row0 = blockIdx.x * BM;

    int *idxs = (int *)(smc + IDXOFF3);
    for (int t = tid; t < SPI * BM; t += 256) {
        int m = t / SPI, s = t % SPI;
        int r = row0 + m;
        if (r >= N) r = N - 1;
        idxs[s * BM + m] = idxg[(size_t)r * SPI + s];
    }
    float *prm = (float *)(smc + PRM3);
    for (int t = tid; t < 384; t += 256) prm[t] = Wf[t];
    if (tid < 3)   prm[384 + tid] = bf[tid];
    if (tid < 128) prm[388 + tid] = b3[tid];
    __syncthreads();

    const char *Xb = (const char *)X + (size_t)b * N * 256;

    if (blockIdx.x < (unsigned)tmSplit) {
        // ================= TENSOR PATH (R10 mma FUSE) =================
        int warpM = wid >> 1, warpN = wid & 1;
        float acc[2][8][4];
#pragma unroll
        for (int mt = 0; mt < 2; mt++)
#pragma unroll
            for (int nf = 0; nf < 8; nf++)
#pragma unroll
                for (int c = 0; c < 4; c++) acc[mt][nf][c] = 0.0f;

        int grow = tid >> 1, ghalf = tid & 1;
        uint32_t lm_row  = (uint32_t)(lane & 15);
        uint32_t lm_half = (uint32_t)(lane >> 4) << 4;

        auto issueA = [&](int s, int st) {
            int r = idxs[s * BM + grow];
            const char *src = Xb + (size_t)r * 256;
            uint32_t ah = sb + (uint32_t)st * 16384;
            uint32_t al = sb + 32768 + (uint32_t)st * 16384;
#pragma unroll
            for (int q = 0; q < 4; q++) {
                int c = ghalf * 4 + q;
                uint32_t so = SMEM_SWIZZLE_128B((uint32_t)(grow * 128 + 16 * c));
                cp16(ah + so, src + 16 * c);
                cp16(al + so, src + 128 + 16 * c);
            }
        };
        issueA(0, 0);
        CP_COMMIT();

        for (int s = 0; s < SPI; s++) {
            int st = s & 1;
            CP_WAIT0();
            __syncthreads();
            if (s + 1 < SPI) { issueA(s + 1, st ^ 1); CP_COMMIT(); }
            uint32_t aH = sb + (uint32_t)st * 16384;
            uint32_t aL = sb + 32768 + (uint32_t)st * 16384;
#pragma unroll
            for (int kc = 0; kc < 4; kc++) {
                uint32_t kcoff = (uint32_t)kc * 32 + lm_half;
                uint32_t Ah[2][4], Al[2][4];
#pragma unroll
                for (int mt = 0; mt < 2; mt++) {
                    uint32_t ro = (uint32_t)(warpM * 32 + mt * 16 + lm_row) * 128 + kcoff;
                    uint32_t so = SMEM_SWIZZLE_128B(ro);
                    ldmx4(Ah[mt][0], Ah[mt][1], Ah[mt][2], Ah[mt][3], aH + so);
                    ldmx4(Al[mt][0], Al[mt][1], Al[mt][2], Al[mt][3], aL + so);
                }
#pragma unroll
                for (int ng = 0; ng < 4; ng++) {
                    int ngg = warpN * 4 + ng;
                    const uint4 *bp = WF + ((((size_t)s * 4 + kc) * 8 + ngg) * 2) * 32 + lane;
                    uint4 qh = __ldg(bp);
                    uint4 ql = __ldg(bp + 32);
#pragma unroll
                    for (int mt = 0; mt < 2; mt++) {
                        mma16816(acc[mt][2 * ng],     Ah[mt], qh.x, qh.z);
                        mma16816(acc[mt][2 * ng + 1], Ah[mt], qh.y, qh.w);
                        mma16816(acc[mt][2 * ng],     Ah[mt], ql.x, ql.z);
                        mma16816(acc[mt][2 * ng + 1], Ah[mt], ql.y, ql.w);
                        mma16816(acc[mt][2 * ng],     Al[mt], qh.x, qh.z);
                        mma16816(acc[mt][2 * ng + 1], Al[mt], qh.y, qh.w);
                    }
                }
            }
        }

        __syncthreads();
        float *Cs = (float *)smc;
#pragma unroll
        for (int mt = 0; mt < 2; mt++) {
            int r = warpM * 32 + mt * 16 + (lane >> 2);
#pragma unroll
            for (int nf = 0; nf < 8; nf++) {
                int c = warpN * 64 + nf * 8 + (lane & 3) * 2;
                Cs[r * CSTR3 + c]           = acc[mt][nf][0] + prm[388 + c];
                Cs[r * CSTR3 + c + 1]       = acc[mt][nf][1] + prm[388 + c + 1];
                Cs[(r + 8) * CSTR3 + c]     = acc[mt][nf][2] + prm[388 + c];
                Cs[(r + 8) * CSTR3 + c + 1] = acc[mt][nf][3] + prm[388 + c + 1];
            }
        }
        __syncthreads();
        if (tid < BM) {
            int r = row0 + tid;
            float o0 = prm[384], o1 = prm[385], o2 = prm[386];
            const float *crow = Cs + tid * CSTR3;
#pragma unroll 16
            for (int k = 0; k < 128; k++) {
                float v = crow[k];
                o0 = fmaf(v, prm[3 * k + 0], o0);
                o1 = fmaf(v, prm[3 * k + 1], o1);
                o2 = fmaf(v, prm[3 * k + 2], o2);
            }
            if (r < N) {
                float *o = out + ((size_t)b * N + r) * 3;
                o[0] = o0; o[1] = o1; o[2] = o2;
            }
        }
    } else {
        // ================= FFMA PATH (R4 micro-kernel) =================
        float *As = (float *)smc;             // [64][128] fp32 = 32KB
        float *Bs = (float *)(smc + 32768);   // [64][128] fp32 = 32KB
        int tx = tid & 15, ty = tid >> 4;
        int m0 = ty * 8, n0 = tx * 4;

        float2 acc[4][8];
#pragma unroll
        for (int g = 0; g < 2; g++)
#pragma unroll
            for (int c = 0; c < 4; c++) {
                float bv = prm[388 + g * 64 + n0 + c];
#pragma unroll
                for (int i = 0; i < 4; i++) acc[i][g * 4 + c] = make_float2(bv, bv);
            }

        int mW = (wid & 3) * 32 + lane;
        int kW = (wid >> 2) * 32;

        for (int s = 0; s < SPI; s++) {
            if (s) __syncthreads();
            // gather + exact hi+lo reconstruct -> fp32 A tile
            {
                int r = idxs[s * BM + mW];
                const char *src = Xb + (size_t)r * 256;
#pragma unroll
                for (int q = 0; q < 4; q++) {
                    uint4 h4 = __ldg((const uint4 *)(src + 2 * kW + 16 * q));
                    uint4 l4 = __ldg((const uint4 *)(src + 128 + 2 * kW + 16 * q));
                    float2 e0 = recon2(h4.x, l4.x);
                    float2 e1 = recon2(h4.y, l4.y);
                    float2 e2 = recon2(h4.z, l4.z);
                    float2 e3 = recon2(h4.w, l4.w);
                    float *d = As + (kW + 8 * q) * BM + mW;
                    d[0 * BM] = e0.x; d[1 * BM] = e0.y;
                    d[2 * BM] = e1.x; d[3 * BM] = e1.y;
                    d[4 * BM] = e2.x; d[5 * BM] = e2.y;
                    d[6 * BM] = e3.x; d[7 * BM] = e3.y;
                }
            }
            // fp32 W tile
            {
                const float *Wt = W3 + (size_t)s * 64 * 128;
#pragma unroll
                for (int t = 4 * tid; t < 64 * 128; t += 1024)
                    *(float4 *)(Bs + t) = __ldg((const float4 *)(Wt + t));
            }
            __syncthreads();
#pragma unroll 4
            for (int k = 0; k < 64; k++) {
                float2 a2[4];
                {
                    float4 v0 = *(const float4 *)(As + k * BM + m0);
                    float4 v1 = *(const float4 *)(As + k * BM + m0 + 4);
                    a2[0] = make_float2(v0.x, v0.y);
                    a2[1] = make_float2(v0.z, v0.w);
                    a2[2] = make_float2(v1.x, v1.y);
                    a2[3] = make_float2(v1.z, v1.w);
                }
                float2 b2[8];
#pragma unroll
                for (int g = 0; g < 2; g++) {
                    float4 t4 = *(const float4 *)(Bs + k * 128 + g * 64 + n0);
                    b2[4 * g + 0] = make_float2(t4.x, t4.x);
                    b2[4 * g + 1] = make_float2(t4.y, t4.y);
                    b2[4 * g + 2] = make_float2(t4.z, t4.z);
                    b2[4 * g + 3] = make_float2(t4.w, t4.w);
                }
#pragma unroll
                for (int i = 0; i < 4; i++)
#pragma unroll
                    for (int j = 0; j < 8; j++) ffma2(acc[i][j], a2[i], b2[j]);
            }
        }

        // fused final linear through smem
        __syncthreads();
        float *Cs = (float *)smc;
#pragma unroll
        for (int i = 0; i < 4; i++)
#pragma unroll
            for (int g = 0; g < 2; g++) {
                int col = g * 64 + n0;
                *(float4 *)(Cs + (m0 + 2 * i) * CSTR3 + col) =
                    make_float4(acc[i][4 * g].x, acc[i][4 * g + 1].x,
                                acc[i][4 * g + 2].x, acc[i][4 * g + 3].x);
                *(float4 *)(Cs + (m0 + 2 * i + 1) * CSTR3 + col) =
                    make_float4(acc[i][4 * g].y, acc[i][4 * g + 1].y,
                                acc[i][4 * g + 2].y, acc[i][4 * g + 3].y);
            }
        __syncthreads();
        if (tid < BM) {
            int r = row0 + tid;
            float o0 = prm[384], o1 = prm[385], o2 = prm[386];
            const float *crow = Cs + tid * CSTR3;
#pragma unroll 16
            for (int k = 0; k < 128; k++) {
                float v = crow[k];
                o0 = fmaf(v, prm[3 * k + 0], o0);
                o1 = fmaf(v, prm[3 * k + 1], o1);
                o2 = fmaf(v, prm[3 * k + 2], o2);
            }
            if (r < N) {
                float *o = out + ((size_t)b * N + r) * 3;
                o[0] = o0; o[1] = o1; o[2] = o2;
            }
        }
    }
}

// ---------------------------------------------------------------------------
extern "C" void kernel_launch(void *const *d_in, const int *in_sizes, int n_in,
                              void *d_out, int out_size) {
    const float *x   = (const float *)d_in[0];
    const int   *idx = (const int *)d_in[1];
    const float *W0  = (const float *)d_in[2];
    const float *b0  = (const float *)d_in[3];
    const float *W1  = (const float *)d_in[4];
    const float *b1  = (const float *)d_in[5];
    const float *W2  = (const float *)d_in[6];
    const float *b2  = (const float *)d_in[7];
    const float *W3  = (const float *)d_in[8];
    const float *b3  = (const float *)d_in[9];
    const float *Wf  = (const float *)d_in[10];
    const float *bf  = (const float *)d_in[11];
    float *out = (float *)d_out;

    int N = in_sizes[1] / SPI;
    int B = in_sizes[0] / (N * 3);

    __nv_bfloat16 *bufX, *bufY;
    cudaGetSymbolAddress((void **)&bufX, g_bufX);
    cudaGetSymbolAddress((void **)&bufY, g_bufY);
    uint4 *wf1, *wf2, *wf3;
    cudaGetSymbolAddress((void **)&wf1, g_WF1);
    cudaGetSymbolAddress((void **)&wf2, g_WF2);
    cudaGetSymbolAddress((void **)&wf3, g_WF3);

    constexpr int SMN1 = 65536 + 4608 + 32 * 4;
    constexpr int SMN2 = 65536 + 4608 + 64 * 4;
    cudaFuncSetAttribute(layer_mma<16, 32>,
                         cudaFuncAttributeMaxDynamicSharedMemorySize, SMN1);
    cudaFuncSetAttribute(layer_mma<32, 64>,
                         cudaFuncAttributeMaxDynamicSharedMemorySize, SMN2);
    cudaFuncSetAttribute(layer3_hybrid,
                         cudaFuncAttributeMaxDynamicSharedMemorySize, SMF3);

    prep_wfrag<16, 32><<<9, 256>>>(W1, wf1);
    prep_wfrag<32, 64><<<9, 256>>>(W2, wf2);
    prep_wfrag<64, 128><<<9, 256>>>(W3, wf3);

    dim3 g0((N + 255) / 256, B);
    layer0_kernel<<<g0, 256>>>(x, idx, W0, b0, bufX, N);

    int tiles = (N + BM - 1) / BM;
    int tmSplit = (tiles * 70 + 50) / 100;   // 70% of tiles on the tensor path
    dim3 gl(tiles, B);
    layer_mma<16, 32><<<gl, 256, SMN1>>>(bufX, idx, b1, wf1, bufY, N);
    layer_mma<32, 64><<<gl, 256, SMN2>>>(bufY, idx, b2, wf2, bufX, N);
    layer3_hybrid<<<gl, 256, SMF3>>>(bufX, idx, b3, wf3, W3, Wf, bf,
                                     out, N, tmSplit);
}

// round 13
// speedup vs baseline: 1.5545x; 1.5545x over previous
#include <cuda_runtime.h>
#include <cuda_fp16.h>
#include <cstddef>
#include <cstdint>

#define SPI 9
#define BM  128

// Activations stored pre-split: per vertex [hi fp16 x C | lo fp16 x C].
__device__ __align__(16) __half g_bufX[(size_t)8 * 50000 * 128]; // L0 out (64B/row) / L2 out (256B/row)
__device__ __align__(16) __half g_bufY[(size_t)8 * 50000 * 64];  // L1 out (128B/row)
// Weights pre-shuffled into mma.sync B-fragment order (single fp16 set):
//   WF[s][kc][ngg][lane] : uint4 = {b_n0_klo, b_n8_klo, b_n0_khi, b_n8_khi}
__device__ __align__(16) uint4 g_WF1[9 * 1 * 2 * 32];
__device__ __align__(16) uint4 g_WF2[9 * 2 * 4 * 32];
__device__ __align__(16) uint4 g_WF3[9 * 4 * 8 * 32];

__device__ __forceinline__ void ffma2(float2 &d, const float2 &a, const float2 &b) {
    unsigned long long       &du = reinterpret_cast<unsigned long long &>(d);
    const unsigned long long &au = reinterpret_cast<const unsigned long long &>(a);
    const unsigned long long &bu = reinterpret_cast<const unsigned long long &>(b);
    asm("fma.rn.f32x2 %0, %1, %2, %0;" : "+l"(du) : "l"(au), "l"(bu));
}
__device__ __forceinline__ uint32_t smem_u32(const void *p) {
    uint32_t a;
    asm("{ .reg .u64 t; cvta.to.shared.u64 t, %1; cvt.u32.u64 %0, t; }" : "=r"(a) : "l"(p));
    return a;
}
#define SMEM_SWIZZLE_128B(o) ((o) ^ (((o) >> 3) & 0x70))

__device__ __forceinline__ void cp16(uint32_t dst, const void *src) {
    asm volatile("cp.async.cg.shared.global [%0], [%1], 16;" :: "r"(dst), "l"(src));
}
#define CP_COMMIT() asm volatile("cp.async.commit_group;" ::: "memory")
#define CP_WAIT0()  asm volatile("cp.async.wait_group 0;" ::: "memory")

__device__ __forceinline__ void ldmx4(uint32_t &r0, uint32_t &r1, uint32_t &r2,
                                      uint32_t &r3, uint32_t addr) {
    asm volatile("ldmatrix.sync.aligned.m8n8.x4.shared.b16 {%0,%1,%2,%3}, [%4];"
                 : "=r"(r0), "=r"(r1), "=r"(r2), "=r"(r3) : "r"(addr));
}
// fp16 inputs, fp32 accumulate
__device__ __forceinline__ void mma16816(float *c, const uint32_t *a,
                                         uint32_t b0, uint32_t b1) {
    asm volatile("mma.sync.aligned.m16n8k16.row.col.f32.f16.f16.f32 "
                 "{%0,%1,%2,%3}, {%4,%5,%6,%7}, {%8,%9}, {%0,%1,%2,%3};"
                 : "+f"(c[0]), "+f"(c[1]), "+f"(c[2]), "+f"(c[3])
                 : "r"(a[0]), "r"(a[1]), "r"(a[2]), "r"(a[3]), "r"(b0), "r"(b1));
}
// split v into hi/lo fp16x2 packed words (A is ~exact: 22 effective bits)
__device__ __forceinline__ void split2(float2 v, uint32_t &h, uint32_t &l) {
    __half2 hb = __float22half2_rn(v);
    float2 hf = __half22float2(hb);
    __half2 lb = __float22half2_rn(make_float2(v.x - hf.x, v.y - hf.y));
    h = *(uint32_t *)&hb;
    l = *(uint32_t *)&lb;
}

// ---------------------------------------------------------------------------
// Layer 0 (FFMA2): Cin=3 -> 16, writes pre-split hi/lo rows (64B/vertex).
// ---------------------------------------------------------------------------
__global__ void layer0_kernel(const float *__restrict__ X, const int *__restrict__ idx,
                              const float *__restrict__ W, const float *__restrict__ bias,
                              __half *__restrict__ Y, int N) {
    __shared__ float Ws[27 * 16];
    __shared__ float bs[16];
    int tid = threadIdx.x;
    for (int t = tid; t < 27 * 16; t += blockDim.x) Ws[t] = W[t];
    if (tid < 16) bs[tid] = bias[tid];
    __syncthreads();

    int n = blockIdx.x * blockDim.x + tid;
    int b = blockIdx.y;
    if (n >= N) return;

    float2 acc[8];
#pragma unroll
    for (int j = 0; j < 8; j++) acc[j] = make_float2(bs[2 * j], bs[2 * j + 1]);

    const float *Xb = X + (size_t)b * N * 3;
#pragma unroll
    for (int s = 0; s < SPI; s++) {
        int r = idx[n * SPI + s];
        float xv[3];
        xv[0] = __ldg(Xb + (size_t)r * 3 + 0);
        xv[1] = __ldg(Xb + (size_t)r * 3 + 1);
        xv[2] = __ldg(Xb + (size_t)r * 3 + 2);
#pragma unroll
        for (int c = 0; c < 3; c++) {
            const float *wrow = Ws + (s * 3 + c) * 16;
            float2 vv = make_float2(xv[c], xv[c]);
#pragma unroll
            for (int j = 0; j < 8; j++) {
                float2 w = *(const float2 *)(wrow + 2 * j);
                ffma2(acc[j], vv, w);
            }
        }
    }
    uint32_t hi[8], lo[8];
#pragma unroll
    for (int j = 0; j < 8; j++) split2(acc[j], hi[j], lo[j]);
    char *y = (char *)Y + ((size_t)b * N + n) * 64;
    *(uint4 *)(y + 0)  = make_uint4(hi[0], hi[1], hi[2], hi[3]);
    *(uint4 *)(y + 16) = make_uint4(hi[4], hi[5], hi[6], hi[7]);
    *(uint4 *)(y + 32) = make_uint4(lo[0], lo[1], lo[2], lo[3]);
    *(uint4 *)(y + 48) = make_uint4(lo[4], lo[5], lo[6], lo[7]);
}

// ---------------------------------------------------------------------------
// Weight prep: W[S*CIN, COUT] -> mma B-fragment order, single fp16.
// entry i within s: lane=i&31, ngg=(i>>5)%NGT, kc=(i>>5)/NGT
// ---------------------------------------------------------------------------
template <int CIN, int COUT>
__global__ void prep_wfrag(const float *__restrict__ W, uint4 *__restrict__ dst) {
    constexpr int KCH = CIN / 16, NGT = COUT / 16;
    constexpr int PER = KCH * NGT * 32;
    int s = blockIdx.x;
    for (int i = threadIdx.x; i < PER; i += blockDim.x) {
        int lane = i & 31, ngg = (i >> 5) % NGT, kc = (i >> 5) / NGT;
        int n0 = ngg * 16 + (lane >> 2);
        int kb = kc * 16 + 2 * (lane & 3);
        auto wsel = [&](int k, int n) -> uint32_t {
            float v = __ldg(W + (size_t)(s * CIN + k) * COUT + n);
            __half hb = __float2half_rn(v);
            return (uint32_t)(*(uint16_t *)&hb);
        };
        auto word = [&](int k, int n) { return wsel(k, n) | (wsel(k + 1, n) << 16); };
        uint4 q;
        q.x = word(kb,     n0);       // n-lo, k-lo
        q.y = word(kb,     n0 + 8);   // n-hi, k-lo
        q.z = word(kb + 8, n0);       // n-lo, k-hi
        q.w = word(kb + 8, n0 + 8);   // n-hi, k-hi
        dst[(size_t)s * PER + i] = q;
    }
}

// ---------------------------------------------------------------------------
// Unified spiral-conv layer: fp16 asymmetric 2-term mma.sync (Ah*B + Al*B).
// A via cp.async double-buffered smem gather; B via per-lane LDG fragments.
// ---------------------------------------------------------------------------
template <int CIN, int COUT, bool FUSE>
__global__ void __launch_bounds__(256, 2)
layer_mma(const __half *__restrict__ X,
          const int   *__restrict__ idxg,
          const float *__restrict__ bias,
          const uint4 *__restrict__ WF,
          const float *__restrict__ Wf,
          const float *__restrict__ bf,
          void *__restrict__ Y,
          int N) {
    constexpr int KCH = CIN / 16;
    constexpr int NGT = COUT / 16;
    constexpr int WN  = (COUT >= 128) ? 2 : 1;
    constexpr int WM  = 8 / WN;
    constexpr int MT  = 128 / (WM * 16);
    constexpr int NG  = NGT / WN;
    constexpr int CB  = 2 * CIN;
    constexpr int CPT = CB / 32;
    constexpr int XROW = 4 * CIN;
    constexpr int IDXOFF = 65536;          // A region: hi st0/st1, lo st0/st1 (4x16KB)
    constexpr int PRM = IDXOFF + 4608;
    constexpr int CSTR = 132;

    extern __shared__ __align__(1024) char smc[];
    uint32_t sb = smem_u32(smc);
    int tid = threadIdx.x, wid = tid >> 5, lane = tid & 31;
    int b = blockIdx.y, row0 = blockIdx.x * BM;
    int warpM = wid / WN, warpN = wid % WN;

    int *idxs = (int *)(smc + IDXOFF);
    for (int t = tid; t < SPI * BM; t += 256) {
        int m = t / SPI, s = t % SPI;
        int r = row0 + m;
        if (r >= N) r = N - 1;
        idxs[s * BM + m] = idxg[(size_t)r * SPI + s];
    }
    float *prm = (float *)(smc + PRM);
    if (FUSE) {
        for (int t = tid; t < 384; t += 256) prm[t] = Wf[t];
        if (tid < 3)    prm[384 + tid] = bf[tid];
        if (tid < COUT) prm[388 + tid] = bias[tid];
    } else {
        if (tid < COUT) prm[tid] = bias[tid];
    }

    float acc[MT][2 * NG][4];
#pragma unroll
    for (int mt = 0; mt < MT; mt++)
#pragma unroll
        for (int nf = 0; nf < 2 * NG; nf++)
#pragma unroll
            for (int c = 0; c < 4; c++) acc[mt][nf][c] = 0.0f;

    const char *Xb = (const char *)X + (size_t)b * N * XROW;
    int grow = tid >> 1, ghalf = tid & 1;
    uint32_t lm_row  = (uint32_t)(lane & 15);
    uint32_t lm_half = (uint32_t)(lane >> 4) << 4;

    __syncthreads();   // idxs ready

    auto issueA = [&](int s, int st) {
        int r = idxs[s * BM + grow];
        const char *src = Xb + (size_t)r * XROW;
        uint32_t ah = sb + (uint32_t)st * 16384;
        uint32_t al = sb + 32768 + (uint32_t)st * 16384;
#pragma unroll
        for (int q = 0; q < CPT; q++) {
            int c = ghalf * CPT + q;
            uint32_t so = SMEM_SWIZZLE_128B((uint32_t)(grow * 128 + 16 * c));
            cp16(ah + so, src + 16 * c);
            cp16(al + so, src + CB + 16 * c);
        }
    };

    issueA(0, 0);
    CP_COMMIT();

    for (int s = 0; s < SPI; s++) {
        int st = s & 1;
        CP_WAIT0();
        __syncthreads();
        if (s + 1 < SPI) {
            issueA(s + 1, st ^ 1);
            CP_COMMIT();
        }
        uint32_t aH = sb + (uint32_t)st * 16384;
        uint32_t aL = sb + 32768 + (uint32_t)st * 16384;
#pragma unroll
        for (int kc = 0; kc < KCH; kc++) {
            uint32_t kcoff = (uint32_t)kc * 32 + lm_half;
            uint32_t Ah[MT][4], Al[MT][4];
#pragma unroll
            for (int mt = 0; mt < MT; mt++) {
                uint32_t ro = (uint32_t)(warpM * (16 * MT) + mt * 16 + lm_row) * 128 + kcoff;
                uint32_t so = SMEM_SWIZZLE_128B(ro);
                ldmx4(Ah[mt][0], Ah[mt][1], Ah[mt][2], Ah[mt][3], aH + so);
                ldmx4(Al[mt][0], Al[mt][1], Al[mt][2], Al[mt][3], aL + so);
            }
#pragma unroll
            for (int ng = 0; ng < NG; ng++) {
                int ngg = warpN * NG + ng;
                const uint4 *bp = WF + (((size_t)s * KCH + kc) * NGT + ngg) * 32 + lane;
                uint4 q = __ldg(bp);
#pragma unroll
                for (int mt = 0; mt < MT; mt++) {
                    mma16816(acc[mt][2 * ng],     Ah[mt], q.x, q.z);
                    mma16816(acc[mt][2 * ng + 1], Ah[mt], q.y, q.w);
                    mma16816(acc[mt][2 * ng],     Al[mt], q.x, q.z);
                    mma16816(acc[mt][2 * ng + 1], Al[mt], q.y, q.w);
                }
            }
        }
    }

    if (!FUSE) {
        char *Yb = (char *)Y + (size_t)b * N * (4 * COUT);
#pragma unroll
        for (int mt = 0; mt < MT; mt++) {
            int rr = row0 + warpM * (16 * MT) + mt * 16 + (lane >> 2);
#pragma unroll
            for (int nf = 0; nf < 2 * NG; nf++) {
                int c = warpN * (COUT / WN) + nf * 8 + (lane & 3) * 2;
                float bv0 = prm[c], bv1 = prm[c + 1];
                uint32_t h, l;
                if (rr < N) {
                    split2(make_float2(acc[mt][nf][0] + bv0, acc[mt][nf][1] + bv1), h, l);
                    char *rp = Yb + (size_t)rr * (4 * COUT);
                    *(uint32_t *)(rp + 2 * c) = h;
                    *(uint32_t *)(rp + 2 * COUT + 2 * c) = l;
                }
                if (rr + 8 < N) {
                    split2(make_float2(acc[mt][nf][2] + bv0, acc[mt][nf][3] + bv1), h, l);
                    char *rp = Yb + (size_t)(rr + 8) * (4 * COUT);
                    *(uint32_t *)(rp + 2 * c) = h;
                    *(uint32_t *)(rp + 2 * COUT + 2 * c) = l;
                }
            }
        }
    } else {
        __syncthreads();
        float *Cs = (float *)smc;   // [128][CSTR] = 67584B; overlaps dead A+idx, not prm
#pragma unroll
        for (int mt = 0; mt < MT; mt++) {
            int r = warpM * (16 * MT) + mt * 16 + (lane >> 2);
#pragma unroll
            for (int nf = 0; nf < 2 * NG; nf++) {
                int c = warpN * (COUT / WN) + nf * 8 + (lane & 3) * 2;
                Cs[r * CSTR + c]           = acc[mt][nf][0] + prm[388 + c];
                Cs[r * CSTR + c + 1]       = acc[mt][nf][1] + prm[388 + c + 1];
                Cs[(r + 8) * CSTR + c]     = acc[mt][nf][2] + prm[388 + c];
                Cs[(r + 8) * CSTR + c + 1] = acc[mt][nf][3] + prm[388 + c + 1];
            }
        }
        __syncthreads();
        if (tid < BM) {
            int r = row0 + tid;
            float o0 = prm[384], o1 = prm[385], o2 = prm[386];
            const float *crow = Cs + tid * CSTR;
#pragma unroll 16
            for (int k = 0; k < COUT; k++) {
                float v = crow[k];
                o0 = fmaf(v, prm[3 * k + 0], o0);
                o1 = fmaf(v, prm[3 * k + 1], o1);
                o2 = fmaf(v, prm[3 * k + 2], o2);
            }
            if (r < N) {
                float *o = (float *)Y + ((size_t)b * N + r) * 3;
                o[0] = o0; o[1] = o1; o[2] = o2;
            }
        }
    }
}

// ---------------------------------------------------------------------------
extern "C" void kernel_launch(void *const *d_in, const int *in_sizes, int n_in,
                              void *d_out, int out_size) {
    const float *x   = (const float *)d_in[0];
    const int   *idx = (const int *)d_in[1];
    const float *W0  = (const float *)d_in[2];
    const float *b0  = (const float *)d_in[3];
    const float *W1  = (const float *)d_in[4];
    const float *b1  = (const float *)d_in[5];
    const float *W2  = (const float *)d_in[6];
    const float *b2  = (const float *)d_in[7];
    const float *W3  = (const float *)d_in[8];
    const float *b3  = (const float *)d_in[9];
    const float *Wf  = (const float *)d_in[10];
    const float *bf  = (const float *)d_in[11];
    float *out = (float *)d_out;

    int N = in_sizes[1] / SPI;
    int B = in_sizes[0] / (N * 3);

    __half *bufX, *bufY;
    cudaGetSymbolAddress((void **)&bufX, g_bufX);
    cudaGetSymbolAddress((void **)&bufY, g_bufY);
    uint4 *wf1, *wf2, *wf3;
    cudaGetSymbolAddress((void **)&wf1, g_WF1);
    cudaGetSymbolAddress((void **)&wf2, g_WF2);
    cudaGetSymbolAddress((void **)&wf3, g_WF3);

    constexpr int SMN1 = 65536 + 4608 + 32 * 4;
    constexpr int SMN2 = 65536 + 4608 + 64 * 4;
    constexpr int SMF  = 65536 + 4608 + (384 + 4 + 128) * 4;
    cudaFuncSetAttribute(layer_mma<16, 32, false>,
                         cudaFuncAttributeMaxDynamicSharedMemorySize, SMN1);
    cudaFuncSetAttribute(layer_mma<32, 64, false>,
                         cudaFuncAttributeMaxDynamicSharedMemorySize, SMN2);
    cudaFuncSetAttribute(layer_mma<64, 128, true>,
                         cudaFuncAttributeMaxDynamicSharedMemorySize, SMF);

    prep_wfrag<16, 32><<<9, 256>>>(W1, wf1);
    prep_wfrag<32, 64><<<9, 256>>>(W2, wf2);
    prep_wfrag<64, 128><<<9, 256>>>(W3, wf3);

    dim3 g0((N + 255) / 256, B);
    layer0_kernel<<<g0, 256>>>(x, idx, W0, b0, bufX, N);

    dim3 gl((N + BM - 1) / BM, B);
    layer_mma<16, 32, false><<<gl, 256, SMN1>>>(bufX, idx, b1, wf1,
                                                nullptr, nullptr, bufY, N);
    layer_mma<32, 64, false><<<gl, 256, SMN2>>>(bufY, idx, b2, wf2,
                                                nullptr, nullptr, bufX, N);
    layer_mma<64, 128, true><<<gl, 256, SMF>>>(bufX, idx, b3, wf3,
                                               Wf, bf, out, N);
}

// round 14
// speedup vs baseline: 1.9893x; 1.2797x over previous
#include <cuda_runtime.h>
#include <cuda_fp16.h>
#include <cstddef>
#include <cstdint>

#define SPI 9
#define BM  128

// Activations stored pre-split: per vertex [hi fp16 x C | lo fp16 x C].
__device__ __align__(16) __half g_bufX[(size_t)8 * 50000 * 128]; // L0 out (64B/row) / L2 out (256B/row)
__device__ __align__(16) __half g_bufY[(size_t)8 * 50000 * 64];  // L1 out (128B/row)
// Weights pre-shuffled into mma.sync B-fragment order (single fp16 set):
__device__ __align__(16) uint4 g_WF1[9 * 1 * 2 * 32];
__device__ __align__(16) uint4 g_WF2[9 * 2 * 4 * 32];
__device__ __align__(16) uint4 g_WF3[9 * 4 * 8 * 32];

__device__ __forceinline__ void ffma2(float2 &d, const float2 &a, const float2 &b) {
    unsigned long long       &du = reinterpret_cast<unsigned long long &>(d);
    const unsigned long long &au = reinterpret_cast<const unsigned long long &>(a);
    const unsigned long long &bu = reinterpret_cast<const unsigned long long &>(b);
    asm("fma.rn.f32x2 %0, %1, %2, %0;" : "+l"(du) : "l"(au), "l"(bu));
}
__device__ __forceinline__ uint32_t smem_u32(const void *p) {
    uint32_t a;
    asm("{ .reg .u64 t; cvta.to.shared.u64 t, %1; cvt.u32.u64 %0, t; }" : "=r"(a) : "l"(p));
    return a;
}
#define SMEM_SWIZZLE_128B(o) ((o) ^ (((o) >> 3) & 0x70))

__device__ __forceinline__ void cp16(uint32_t dst, const void *src) {
    asm volatile("cp.async.cg.shared.global [%0], [%1], 16;" :: "r"(dst), "l"(src));
}
#define CP_COMMIT() asm volatile("cp.async.commit_group;" ::: "memory")
#define CP_WAIT0()  asm volatile("cp.async.wait_group 0;" ::: "memory")

__device__ __forceinline__ void ldmx4(uint32_t &r0, uint32_t &r1, uint32_t &r2,
                                      uint32_t &r3, uint32_t addr) {
    asm volatile("ldmatrix.sync.aligned.m8n8.x4.shared.b16 {%0,%1,%2,%3}, [%4];"
                 : "=r"(r0), "=r"(r1), "=r"(r2), "=r"(r3) : "r"(addr));
}
// fp16 inputs, fp32 accumulate
__device__ __forceinline__ void mma16816(float *c, const uint32_t *a,
                                         uint32_t b0, uint32_t b1) {
    asm volatile("mma.sync.aligned.m16n8k16.row.col.f32.f16.f16.f32 "
                 "{%0,%1,%2,%3}, {%4,%5,%6,%7}, {%8,%9}, {%0,%1,%2,%3};"
                 : "+f"(c[0]), "+f"(c[1]), "+f"(c[2]), "+f"(c[3])
                 : "r"(a[0]), "r"(a[1]), "r"(a[2]), "r"(a[3]), "r"(b0), "r"(b1));
}
// split v into hi/lo fp16x2 packed words (A pair is ~exact: 22 effective bits)
__device__ __forceinline__ void split2(float2 v, uint32_t &h, uint32_t &l) {
    __half2 hb = __float22half2_rn(v);
    float2 hf = __half22float2(hb);
    __half2 lb = __float22half2_rn(make_float2(v.x - hf.x, v.y - hf.y));
    h = *(uint32_t *)&hb;
    l = *(uint32_t *)&lb;
}

// ---------------------------------------------------------------------------
// Layer 0 (FFMA2): Cin=3 -> 16, writes pre-split hi/lo rows (64B/vertex).
// ---------------------------------------------------------------------------
__global__ void layer0_kernel(const float *__restrict__ X, const int *__restrict__ idx,
                              const float *__restrict__ W, const float *__restrict__ bias,
                              __half *__restrict__ Y, int N) {
    __shared__ float Ws[27 * 16];
    __shared__ float bs[16];
    int tid = threadIdx.x;
    for (int t = tid; t < 27 * 16; t += blockDim.x) Ws[t] = W[t];
    if (tid < 16) bs[tid] = bias[tid];
    __syncthreads();

    int n = blockIdx.x * blockDim.x + tid;
    int b = blockIdx.y;
    if (n >= N) return;

    float2 acc[8];
#pragma unroll
    for (int j = 0; j < 8; j++) acc[j] = make_float2(bs[2 * j], bs[2 * j + 1]);

    const float *Xb = X + (size_t)b * N * 3;
#pragma unroll
    for (int s = 0; s < SPI; s++) {
        int r = idx[n * SPI + s];
        float xv[3];
        xv[0] = __ldg(Xb + (size_t)r * 3 + 0);
        xv[1] = __ldg(Xb + (size_t)r * 3 + 1);
        xv[2] = __ldg(Xb + (size_t)r * 3 + 2);
#pragma unroll
        for (int c = 0; c < 3; c++) {
            const float *wrow = Ws + (s * 3 + c) * 16;
            float2 vv = make_float2(xv[c], xv[c]);
#pragma unroll
            for (int j = 0; j < 8; j++) {
                float2 w = *(const float2 *)(wrow + 2 * j);
                ffma2(acc[j], vv, w);
            }
        }
    }
    uint32_t hi[8], lo[8];
#pragma unroll
    for (int j = 0; j < 8; j++) split2(acc[j], hi[j], lo[j]);
    char *y = (char *)Y + ((size_t)b * N + n) * 64;
    *(uint4 *)(y + 0)  = make_uint4(hi[0], hi[1], hi[2], hi[3]);
    *(uint4 *)(y + 16) = make_uint4(hi[4], hi[5], hi[6], hi[7]);
    *(uint4 *)(y + 32) = make_uint4(lo[0], lo[1], lo[2], lo[3]);
    *(uint4 *)(y + 48) = make_uint4(lo[4], lo[5], lo[6], lo[7]);
}

// ---------------------------------------------------------------------------
// Weight prep: W[S*CIN, COUT] -> mma B-fragment order, single fp16.
// ---------------------------------------------------------------------------
template <int CIN, int COUT>
__global__ void prep_wfrag(const float *__restrict__ W, uint4 *__restrict__ dst) {
    constexpr int KCH = CIN / 16, NGT = COUT / 16;
    constexpr int PER = KCH * NGT * 32;
    int s = blockIdx.x;
    for (int i = threadIdx.x; i < PER; i += blockDim.x) {
        int lane = i & 31, ngg = (i >> 5) % NGT, kc = (i >> 5) / NGT;
        int n0 = ngg * 16 + (lane >> 2);
        int kb = kc * 16 + 2 * (lane & 3);
        auto wsel = [&](int k, int n) -> uint32_t {
            float v = __ldg(W + (size_t)(s * CIN + k) * COUT + n);
            __half hb = __float2half_rn(v);
            return (uint32_t)(*(uint16_t *)&hb);
        };
        auto word = [&](int k, int n) { return wsel(k, n) | (wsel(k + 1, n) << 16); };
        uint4 q;
        q.x = word(kb,     n0);
        q.y = word(kb,     n0 + 8);
        q.z = word(kb + 8, n0);
        q.w = word(kb + 8, n0 + 8);
        dst[(size_t)s * PER + i] = q;
    }
}

// ---------------------------------------------------------------------------
// Unified spiral-conv layer: fp16 mma.sync.
//   ATERMS=2: Ah*B + Al*B (A exact to 22 bits)
//   ATERMS=1: Ah*B only (adds one ~2e-4 RMS error source, halves MMA count)
// ---------------------------------------------------------------------------
template <int CIN, int COUT, int ATERMS, bool FUSE>
__global__ void __launch_bounds__(256, 2)
layer_mma(const __half *__restrict__ X,
          const int   *__restrict__ idxg,
          const float *__restrict__ bias,
          const uint4 *__restrict__ WF,
          const float *__restrict__ Wf,
          const float *__restrict__ bf,
          void *__restrict__ Y,
          int N) {
    constexpr int KCH = CIN / 16;
    constexpr int NGT = COUT / 16;
    constexpr int WN  = (COUT >= 128) ? 2 : 1;
    constexpr int WM  = 8 / WN;
    constexpr int MT  = 128 / (WM * 16);
    constexpr int NG  = NGT / WN;
    constexpr int CB  = 2 * CIN;
    constexpr int CPT = CB / 32;
    constexpr int XROW = 4 * CIN;
    constexpr int IDXOFF = 65536;
    constexpr int PRM = IDXOFF + 4608;
    constexpr int CSTR = 132;

    extern __shared__ __align__(1024) char smc[];
    uint32_t sb = smem_u32(smc);
    int tid = threadIdx.x, wid = tid >> 5, lane = tid & 31;
    int b = blockIdx.y, row0 = blockIdx.x * BM;
    int warpM = wid / WN, warpN = wid % WN;

    int *idxs = (int *)(smc + IDXOFF);
    for (int t = tid; t < SPI * BM; t += 256) {
        int m = t / SPI, s = t % SPI;
        int r = row0 + m;
        if (r >= N) r = N - 1;
        idxs[s * BM + m] = idxg[(size_t)r * SPI + s];
    }
    float *prm = (float *)(smc + PRM);
    if (FUSE) {
        for (int t = tid; t < 384; t += 256) prm[t] = Wf[t];
        if (tid < 3)    prm[384 + tid] = bf[tid];
        if (tid < COUT) prm[388 + tid] = bias[tid];
    } else {
        if (tid < COUT) prm[tid] = bias[tid];
    }

    float acc[MT][2 * NG][4];
#pragma unroll
    for (int mt = 0; mt < MT; mt++)
#pragma unroll
        for (int nf = 0; nf < 2 * NG; nf++)
#pragma unroll
            for (int c = 0; c < 4; c++) acc[mt][nf][c] = 0.0f;

    const char *Xb = (const char *)X + (size_t)b * N * XROW;
    int grow = tid >> 1, ghalf = tid & 1;
    uint32_t lm_row  = (uint32_t)(lane & 15);
    uint32_t lm_half = (uint32_t)(lane >> 4) << 4;

    __syncthreads();   // idxs ready

    auto issueA = [&](int s, int st) {
        int r = idxs[s * BM + grow];
        const char *src = Xb + (size_t)r * XROW;
        uint32_t ah = sb + (uint32_t)st * 16384;
        uint32_t al = sb + 32768 + (uint32_t)st * 16384;
#pragma unroll
        for (int q = 0; q < CPT; q++) {
            int c = ghalf * CPT + q;
            uint32_t so = SMEM_SWIZZLE_128B((uint32_t)(grow * 128 + 16 * c));
            cp16(ah + so, src + 16 * c);
            if (ATERMS == 2) cp16(al + so, src + CB + 16 * c);
        }
    };

    issueA(0, 0);
    CP_COMMIT();

    for (int s = 0; s < SPI; s++) {
        int st = s & 1;
        CP_WAIT0();
        __syncthreads();
        if (s + 1 < SPI) {
            issueA(s + 1, st ^ 1);
            CP_COMMIT();
        }
        uint32_t aH = sb + (uint32_t)st * 16384;
        uint32_t aL = sb + 32768 + (uint32_t)st * 16384;
#pragma unroll
        for (int kc = 0; kc < KCH; kc++) {
            uint32_t kcoff = (uint32_t)kc * 32 + lm_half;
            uint32_t Ah[MT][4], Al[MT][4];
#pragma unroll
            for (int mt = 0; mt < MT; mt++) {
                uint32_t ro = (uint32_t)(warpM * (16 * MT) + mt * 16 + lm_row) * 128 + kcoff;
                uint32_t so = SMEM_SWIZZLE_128B(ro);
                ldmx4(Ah[mt][0], Ah[mt][1], Ah[mt][2], Ah[mt][3], aH + so);
                if (ATERMS == 2)
                    ldmx4(Al[mt][0], Al[mt][1], Al[mt][2], Al[mt][3], aL + so);
            }
#pragma unroll
            for (int ng = 0; ng < NG; ng++) {
                int ngg = warpN * NG + ng;
                const uint4 *bp = WF + (((size_t)s * KCH + kc) * NGT + ngg) * 32 + lane;
                uint4 q = __ldg(bp);
#pragma unroll
                for (int mt = 0; mt < MT; mt++) {
                    mma16816(acc[mt][2 * ng],     Ah[mt], q.x, q.z);
                    mma16816(acc[mt][2 * ng + 1], Ah[mt], q.y, q.w);
                    if (ATERMS == 2) {
                        mma16816(acc[mt][2 * ng],     Al[mt], q.x, q.z);
                        mma16816(acc[mt][2 * ng + 1], Al[mt], q.y, q.w);
                    }
                }
            }
        }
    }

    if (!FUSE) {
        char *Yb = (char *)Y + (size_t)b * N * (4 * COUT);
#pragma unroll
        for (int mt = 0; mt < MT; mt++) {
            int rr = row0 + warpM * (16 * MT) + mt * 16 + (lane >> 2);
#pragma unroll
            for (int nf = 0; nf < 2 * NG; nf++) {
                int c = warpN * (COUT / WN) + nf * 8 + (lane & 3) * 2;
                float bv0 = prm[c], bv1 = prm[c + 1];
                uint32_t h, l;
                if (rr < N) {
                    split2(make_float2(acc[mt][nf][0] + bv0, acc[mt][nf][1] + bv1), h, l);
                    char *rp = Yb + (size_t)rr * (4 * COUT);
                    *(uint32_t *)(rp + 2 * c) = h;
                    *(uint32_t *)(rp + 2 * COUT + 2 * c) = l;
                }
                if (rr + 8 < N) {
                    split2(make_float2(acc[mt][nf][2] + bv0, acc[mt][nf][3] + bv1), h, l);
                    char *rp = Yb + (size_t)(rr + 8) * (4 * COUT);
                    *(uint32_t *)(rp + 2 * c) = h;
                    *(uint32_t *)(rp + 2 * COUT + 2 * c) = l;
                }
            }
        }
    } else {
        __syncthreads();
        float *Cs = (float *)smc;   // [128][CSTR] = 67584B; overlaps dead A+idx, not prm
#pragma unroll
        for (int mt = 0; mt < MT; mt++) {
            int r = warpM * (16 * MT) + mt * 16 + (lane >> 2);
#pragma unroll
            for (int nf = 0; nf < 2 * NG; nf++) {
                int c = warpN * (COUT / WN) + nf * 8 + (lane & 3) * 2;
                Cs[r * CSTR + c]           = acc[mt][nf][0] + prm[388 + c];
                Cs[r * CSTR + c + 1]       = acc[mt][nf][1] + prm[388 + c + 1];
                Cs[(r + 8) * CSTR + c]     = acc[mt][nf][2] + prm[388 + c];
                Cs[(r + 8) * CSTR + c + 1] = acc[mt][nf][3] + prm[388 + c + 1];
            }
        }
        __syncthreads();
        if (tid < BM) {
            int r = row0 + tid;
            float o0 = prm[384], o1 = prm[385], o2 = prm[386];
            const float *crow = Cs + tid * CSTR;
#pragma unroll 16
            for (int k = 0; k < COUT; k++) {
                float v = crow[k];
                o0 = fmaf(v, prm[3 * k + 0], o0);
                o1 = fmaf(v, prm[3 * k + 1], o1);
                o2 = fmaf(v, prm[3 * k + 2], o2);
            }
            if (r < N) {
                float *o = (float *)Y + ((size_t)b * N + r) * 3;
                o[0] = o0; o[1] = o1; o[2] = o2;
            }
        }
    }
}

// ---------------------------------------------------------------------------
extern "C" void kernel_launch(void *const *d_in, const int *in_sizes, int n_in,
                              void *d_out, int out_size) {
    const float *x   = (const float *)d_in[0];
    const int   *idx = (const int *)d_in[1];
    const float *W0  = (const float *)d_in[2];
    const float *b0  = (const float *)d_in[3];
    const float *W1  = (const float *)d_in[4];
    const float *b1  = (const float *)d_in[5];
    const float *W2  = (const float *)d_in[6];
    const float *b2  = (const float *)d_in[7];
    const float *W3  = (const float *)d_in[8];
    const float *b3  = (const float *)d_in[9];
    const float *Wf  = (const float *)d_in[10];
    const float *bf  = (const float *)d_in[11];
    float *out = (float *)d_out;

    int N = in_sizes[1] / SPI;
    int B = in_sizes[0] / (N * 3);

    __half *bufX, *bufY;
    cudaGetSymbolAddress((void **)&bufX, g_bufX);
    cudaGetSymbolAddress((void **)&bufY, g_bufY);
    uint4 *wf1, *wf2, *wf3;
    cudaGetSymbolAddress((void **)&wf1, g_WF1);
    cudaGetSymbolAddress((void **)&wf2, g_WF2);
    cudaGetSymbolAddress((void **)&wf3, g_WF3);

    constexpr int SMN1 = 65536 + 4608 + 32 * 4;
    constexpr int SMN2 = 65536 + 4608 + 64 * 4;
    constexpr int SMF  = 65536 + 4608 + (384 + 4 + 128) * 4;
    cudaFuncSetAttribute(layer_mma<16, 32, 2, false>,
                         cudaFuncAttributeMaxDynamicSharedMemorySize, SMN1);
    cudaFuncSetAttribute(layer_mma<32, 64, 2, false>,
                         cudaFuncAttributeMaxDynamicSharedMemorySize, SMN2);
    cudaFuncSetAttribute(layer_mma<64, 128, 1, true>,
                         cudaFuncAttributeMaxDynamicSharedMemorySize, SMF);

    prep_wfrag<16, 32><<<9, 256>>>(W1, wf1);
    prep_wfrag<32, 64><<<9, 256>>>(W2, wf2);
    prep_wfrag<64, 128><<<9, 256>>>(W3, wf3);

    dim3 g0((N + 255) / 256, B);
    layer0_kernel<<<g0, 256>>>(x, idx, W0, b0, bufX, N);

    dim3 gl((N + BM - 1) / BM, B);
    layer_mma<16, 32, 2, false><<<gl, 256, SMN1>>>(bufX, idx, b1, wf1,
                                                   nullptr, nullptr, bufY, N);
    layer_mma<32, 64, 2, false><<<gl, 256, SMN2>>>(bufY, idx, b2, wf2,
                                                   nullptr, nullptr, bufX, N);
    layer_mma<64, 128, 1, true><<<gl, 256, SMF>>>(bufX, idx, b3, wf3,
                                                  Wf, bf, out, N);
}

// round 15
// speedup vs baseline: 2.4151x; 1.2140x over previous
#include <cuda_runtime.h>
#include <cuda_fp16.h>
#include <cstddef>
#include <cstdint>

#define SPI 9
#define BM  128

// Activations stored as fp16 (hi-only): per vertex [fp16 x C].
__device__ __align__(16) __half g_bufX[(size_t)8 * 50000 * 64]; // L0 out (32B/row) / L2 out (128B/row)
__device__ __align__(16) __half g_bufY[(size_t)8 * 50000 * 32]; // L1 out (64B/row)
// Weights pre-shuffled into mma.sync B-fragment order (single fp16 set):
__device__ __align__(16) uint4 g_WF1[9 * 1 * 2 * 32];
__device__ __align__(16) uint4 g_WF2[9 * 2 * 4 * 32];
__device__ __align__(16) uint4 g_WF3[9 * 4 * 8 * 32];

__device__ __forceinline__ void ffma2(float2 &d, const float2 &a, const float2 &b) {
    unsigned long long       &du = reinterpret_cast<unsigned long long &>(d);
    const unsigned long long &au = reinterpret_cast<const unsigned long long &>(a);
    const unsigned long long &bu = reinterpret_cast<const unsigned long long &>(b);
    asm("fma.rn.f32x2 %0, %1, %2, %0;" : "+l"(du) : "l"(au), "l"(bu));
}
__device__ __forceinline__ uint32_t smem_u32(const void *p) {
    uint32_t a;
    asm("{ .reg .u64 t; cvta.to.shared.u64 t, %1; cvt.u32.u64 %0, t; }" : "=r"(a) : "l"(p));
    return a;
}
#define SMEM_SWIZZLE_128B(o) ((o) ^ (((o) >> 3) & 0x70))

__device__ __forceinline__ void cp16(uint32_t dst, const void *src) {
    asm volatile("cp.async.cg.shared.global [%0], [%1], 16;" :: "r"(dst), "l"(src));
}
#define CP_COMMIT() asm volatile("cp.async.commit_group;" ::: "memory")
#define CP_WAIT0()  asm volatile("cp.async.wait_group 0;" ::: "memory")

__device__ __forceinline__ void ldmx4(uint32_t &r0, uint32_t &r1, uint32_t &r2,
                                      uint32_t &r3, uint32_t addr) {
    asm volatile("ldmatrix.sync.aligned.m8n8.x4.shared.b16 {%0,%1,%2,%3}, [%4];"
                 : "=r"(r0), "=r"(r1), "=r"(r2), "=r"(r3) : "r"(addr));
}
// fp16 inputs, fp32 accumulate
__device__ __forceinline__ void mma16816(float *c, const uint32_t *a,
                                         uint32_t b0, uint32_t b1) {
    asm volatile("mma.sync.aligned.m16n8k16.row.col.f32.f16.f16.f32 "
                 "{%0,%1,%2,%3}, {%4,%5,%6,%7}, {%8,%9}, {%0,%1,%2,%3};"
                 : "+f"(c[0]), "+f"(c[1]), "+f"(c[2]), "+f"(c[3])
                 : "r"(a[0]), "r"(a[1]), "r"(a[2]), "r"(a[3]), "r"(b0), "r"(b1));
}
__device__ __forceinline__ uint32_t pack_h2(float2 v) {
    __half2 hb = __float22half2_rn(v);
    return *(uint32_t *)&hb;
}

// ---------------------------------------------------------------------------
// Layer 0 (FFMA2): Cin=3 -> 16, writes fp16 rows (32B/vertex).
// ---------------------------------------------------------------------------
__global__ void layer0_kernel(const float *__restrict__ X, const int *__restrict__ idx,
                              const float *__restrict__ W, const float *__restrict__ bias,
                              __half *__restrict__ Y, int N) {
    __shared__ float Ws[27 * 16];
    __shared__ float bs[16];
    int tid = threadIdx.x;
    for (int t = tid; t < 27 * 16; t += blockDim.x) Ws[t] = W[t];
    if (tid < 16) bs[tid] = bias[tid];
    __syncthreads();

    int n = blockIdx.x * blockDim.x + tid;
    int b = blockIdx.y;
    if (n >= N) return;

    float2 acc[8];
#pragma unroll
    for (int j = 0; j < 8; j++) acc[j] = make_float2(bs[2 * j], bs[2 * j + 1]);

    const float *Xb = X + (size_t)b * N * 3;
#pragma unroll
    for (int s = 0; s < SPI; s++) {
        int r = idx[n * SPI + s];
        float xv[3];
        xv[0] = __ldg(Xb + (size_t)r * 3 + 0);
        xv[1] = __ldg(Xb + (size_t)r * 3 + 1);
        xv[2] = __ldg(Xb + (size_t)r * 3 + 2);
#pragma unroll
        for (int c = 0; c < 3; c++) {
            const float *wrow = Ws + (s * 3 + c) * 16;
            float2 vv = make_float2(xv[c], xv[c]);
#pragma unroll
            for (int j = 0; j < 8; j++) {
                float2 w = *(const float2 *)(wrow + 2 * j);
                ffma2(acc[j], vv, w);
            }
        }
    }
    uint32_t hw[8];
#pragma unroll
    for (int j = 0; j < 8; j++) hw[j] = pack_h2(acc[j]);
    char *y = (char *)Y + ((size_t)b * N + n) * 32;
    *(uint4 *)(y + 0)  = make_uint4(hw[0], hw[1], hw[2], hw[3]);
    *(uint4 *)(y + 16) = make_uint4(hw[4], hw[5], hw[6], hw[7]);
}

// ---------------------------------------------------------------------------
// Weight prep: W[S*CIN, COUT] -> mma B-fragment order, single fp16.
// ---------------------------------------------------------------------------
template <int CIN, int COUT>
__global__ void prep_wfrag(const float *__restrict__ W, uint4 *__restrict__ dst) {
    constexpr int KCH = CIN / 16, NGT = COUT / 16;
    constexpr int PER = KCH * NGT * 32;
    int s = blockIdx.x;
    for (int i = threadIdx.x; i < PER; i += blockDim.x) {
        int lane = i & 31, ngg = (i >> 5) % NGT, kc = (i >> 5) / NGT;
        int n0 = ngg * 16 + (lane >> 2);
        int kb = kc * 16 + 2 * (lane & 3);
        auto wsel = [&](int k, int n) -> uint32_t {
            float v = __ldg(W + (size_t)(s * CIN + k) * COUT + n);
            __half hb = __float2half_rn(v);
            return (uint32_t)(*(uint16_t *)&hb);
        };
        auto word = [&](int k, int n) { return wsel(k, n) | (wsel(k + 1, n) << 16); };
        uint4 q;
        q.x = word(kb,     n0);
        q.y = word(kb,     n0 + 8);
        q.z = word(kb + 8, n0);
        q.w = word(kb + 8, n0 + 8);
        dst[(size_t)s * PER + i] = q;
    }
}

// ---------------------------------------------------------------------------
// Unified spiral-conv layer: fp16 1-term mma.sync (A*B, both single fp16).
// A via cp.async double-buffered smem gather; B via per-lane LDG fragments.
// ---------------------------------------------------------------------------
template <int CIN, int COUT, bool FUSE>
__global__ void __launch_bounds__(256, 2)
layer_mma(const __half *__restrict__ X,
          const int   *__restrict__ idxg,
          const float *__restrict__ bias,
          const uint4 *__restrict__ WF,
          const float *__restrict__ Wf,
          const float *__restrict__ bf,
          void *__restrict__ Y,
          int N) {
    constexpr int KCH = CIN / 16;
    constexpr int NGT = COUT / 16;
    constexpr int WN  = (COUT >= 128) ? 2 : 1;
    constexpr int WM  = 8 / WN;
    constexpr int MT  = 128 / (WM * 16);
    constexpr int NG  = NGT / WN;
    constexpr int CB  = 2 * CIN;           // bytes per source row (fp16 hi-only)
    constexpr int CPT = CB / 32;           // 16B chunks per thread (2 thr/row)
    constexpr int XROW = 2 * CIN;
    constexpr int IDXOFF = 65536;          // A region: st0/st1 (2x16KB used)
    constexpr int PRM = IDXOFF + 4608;
    constexpr int CSTR = 132;

    extern __shared__ __align__(1024) char smc[];
    uint32_t sb = smem_u32(smc);
    int tid = threadIdx.x, wid = tid >> 5, lane = tid & 31;
    int b = blockIdx.y, row0 = blockIdx.x * BM;
    int warpM = wid / WN, warpN = wid % WN;

    int *idxs = (int *)(smc + IDXOFF);
    for (int t = tid; t < SPI * BM; t += 256) {
        int m = t / SPI, s = t % SPI;
        int r = row0 + m;
        if (r >= N) r = N - 1;
        idxs[s * BM + m] = idxg[(size_t)r * SPI + s];
    }
    float *prm = (float *)(smc + PRM);
    if (FUSE) {
        for (int t = tid; t < 384; t += 256) prm[t] = Wf[t];
        if (tid < 3)    prm[384 + tid] = bf[tid];
        if (tid < COUT) prm[388 + tid] = bias[tid];
    } else {
        if (tid < COUT) prm[tid] = bias[tid];
    }

    float acc[MT][2 * NG][4];
#pragma unroll
    for (int mt = 0; mt < MT; mt++)
#pragma unroll
        for (int nf = 0; nf < 2 * NG; nf++)
#pragma unroll
            for (int c = 0; c < 4; c++) acc[mt][nf][c] = 0.0f;

    const char *Xb = (const char *)X + (size_t)b * N * XROW;
    int grow = tid >> 1, ghalf = tid & 1;
    uint32_t lm_row  = (uint32_t)(lane & 15);
    uint32_t lm_half = (uint32_t)(lane >> 4) << 4;

    __syncthreads();   // idxs ready

    auto issueA = [&](int s, int st) {
        int r = idxs[s * BM + grow];
        const char *src = Xb + (size_t)r * XROW;
        uint32_t ah = sb + (uint32_t)st * 16384;
#pragma unroll
        for (int q = 0; q < CPT; q++) {
            int c = ghalf * CPT + q;
            uint32_t so = SMEM_SWIZZLE_128B((uint32_t)(grow * 128 + 16 * c));
            cp16(ah + so, src + 16 * c);
        }
    };

    issueA(0, 0);
    CP_COMMIT();

    for (int s = 0; s < SPI; s++) {
        int st = s & 1;
        CP_WAIT0();
        __syncthreads();
        if (s + 1 < SPI) {
            issueA(s + 1, st ^ 1);
            CP_COMMIT();
        }
        uint32_t aH = sb + (uint32_t)st * 16384;
#pragma unroll
        for (int kc = 0; kc < KCH; kc++) {
            uint32_t kcoff = (uint32_t)kc * 32 + lm_half;
            uint32_t Ah[MT][4];
#pragma unroll
            for (int mt = 0; mt < MT; mt++) {
                uint32_t ro = (uint32_t)(warpM * (16 * MT) + mt * 16 + lm_row) * 128 + kcoff;
                uint32_t so = SMEM_SWIZZLE_128B(ro);
                ldmx4(Ah[mt][0], Ah[mt][1], Ah[mt][2], Ah[mt][3], aH + so);
            }
#pragma unroll
            for (int ng = 0; ng < NG; ng++) {
                int ngg = warpN * NG + ng;
                const uint4 *bp = WF + (((size_t)s * KCH + kc) * NGT + ngg) * 32 + lane;
                uint4 q = __ldg(bp);
#pragma unroll
                for (int mt = 0; mt < MT; mt++) {
                    mma16816(acc[mt][2 * ng],     Ah[mt], q.x, q.z);
                    mma16816(acc[mt][2 * ng + 1], Ah[mt], q.y, q.w);
                }
            }
        }
    }

    if (!FUSE) {
        // write fp16 rows (+bias)
        char *Yb = (char *)Y + (size_t)b * N * (2 * COUT);
#pragma unroll
        for (int mt = 0; mt < MT; mt++) {
            int rr = row0 + warpM * (16 * MT) + mt * 16 + (lane >> 2);
#pragma unroll
            for (int nf = 0; nf < 2 * NG; nf++) {
                int c = warpN * (COUT / WN) + nf * 8 + (lane & 3) * 2;
                float bv0 = prm[c], bv1 = prm[c + 1];
                if (rr < N) {
                    uint32_t h = pack_h2(make_float2(acc[mt][nf][0] + bv0,
                                                     acc[mt][nf][1] + bv1));
                    *(uint32_t *)(Yb + (size_t)rr * (2 * COUT) + 2 * c) = h;
                }
                if (rr + 8 < N) {
                    uint32_t h = pack_h2(make_float2(acc[mt][nf][2] + bv0,
                                                     acc[mt][nf][3] + bv1));
                    *(uint32_t *)(Yb + (size_t)(rr + 8) * (2 * COUT) + 2 * c) = h;
                }
            }
        }
    } else {
        __syncthreads();
        float *Cs = (float *)smc;   // [128][CSTR] = 67584B; overlaps dead A+idx, not prm
#pragma unroll
        for (int mt = 0; mt < MT; mt++) {
            int r = warpM * (16 * MT) + mt * 16 + (lane >> 2);
#pragma unroll
            for (int nf = 0; nf < 2 * NG; nf++) {
                int c = warpN * (COUT / WN) + nf * 8 + (lane & 3) * 2;
                Cs[r * CSTR + c]           = acc[mt][nf][0] + prm[388 + c];
                Cs[r * CSTR + c + 1]       = acc[mt][nf][1] + prm[388 + c + 1];
                Cs[(r + 8) * CSTR + c]     = acc[mt][nf][2] + prm[388 + c];
                Cs[(r + 8) * CSTR + c + 1] = acc[mt][nf][3] + prm[388 + c + 1];
            }
        }
        __syncthreads();
        if (tid < BM) {
            int r = row0 + tid;
            float o0 = prm[384], o1 = prm[385], o2 = prm[386];
            const float *crow = Cs + tid * CSTR;
#pragma unroll 16
            for (int k = 0; k < COUT; k++) {
                float v = crow[k];
                o0 = fmaf(v, prm[3 * k + 0], o0);
                o1 = fmaf(v, prm[3 * k + 1], o1);
                o2 = fmaf(v, prm[3 * k + 2], o2);
            }
            if (r < N) {
                float *o = (float *)Y + ((size_t)b * N + r) * 3;
                o[0] = o0; o[1] = o1; o[2] = o2;
            }
        }
    }
}

// ---------------------------------------------------------------------------
extern "C" void kernel_launch(void *const *d_in, const int *in_sizes, int n_in,
                              void *d_out, int out_size) {
    const float *x   = (const float *)d_in[0];
    const int   *idx = (const int *)d_in[1];
    const float *W0  = (const float *)d_in[2];
    const float *b0  = (const float *)d_in[3];
    const float *W1  = (const float *)d_in[4];
    const float *b1  = (const float *)d_in[5];
    const float *W2  = (const float *)d_in[6];
    const float *b2  = (const float *)d_in[7];
    const float *W3  = (const float *)d_in[8];
    const float *b3  = (const float *)d_in[9];
    const float *Wf  = (const float *)d_in[10];
    const float *bf  = (const float *)d_in[11];
    float *out = (float *)d_out;

    int N = in_sizes[1] / SPI;
    int B = in_sizes[0] / (N * 3);

    __half *bufX, *bufY;
    cudaGetSymbolAddress((void **)&bufX, g_bufX);
    cudaGetSymbolAddress((void **)&bufY, g_bufY);
    uint4 *wf1, *wf2, *wf3;
    cudaGetSymbolAddress((void **)&wf1, g_WF1);
    cudaGetSymbolAddress((void **)&wf2, g_WF2);
    cudaGetSymbolAddress((void **)&wf3, g_WF3);

    constexpr int SMN1 = 65536 + 4608 + 32 * 4;
    constexpr int SMN2 = 65536 + 4608 + 64 * 4;
    constexpr int SMF  = 65536 + 4608 + (384 + 4 + 128) * 4;
    cudaFuncSetAttribute(layer_mma<16, 32, false>,
                         cudaFuncAttributeMaxDynamicSharedMemorySize, SMN1);
    cudaFuncSetAttribute(layer_mma<32, 64, false>,
                         cudaFuncAttributeMaxDynamicSharedMemorySize, SMN2);
    cudaFuncSetAttribute(layer_mma<64, 128, true>,
                         cudaFuncAttributeMaxDynamicSharedMemorySize, SMF);

    prep_wfrag<16, 32><<<9, 256>>>(W1, wf1);
    prep_wfrag<32, 64><<<9, 256>>>(W2, wf2);
    prep_wfrag<64, 128><<<9, 256>>>(W3, wf3);

    dim3 g0((N + 255) / 256, B);
    layer0_kernel<<<g0, 256>>>(x, idx, W0, b0, bufX, N);

    dim3 gl((N + BM - 1) / BM, B);
    layer_mma<16, 32, false><<<gl, 256, SMN1>>>(bufX, idx, b1, wf1,
                                                nullptr, nullptr, bufY, N);
    layer_mma<32, 64, false><<<gl, 256, SMN2>>>(bufY, idx, b2, wf2,
                                                nullptr, nullptr, bufX, N);
    layer_mma<64, 128, true><<<gl, 256, SMF>>>(bufX, idx, b3, wf3,
                                               Wf, bf, out, N);
}

// round 16
// speedup vs baseline: 2.5077x; 1.0384x over previous
#include <cuda_runtime.h>
#include <cuda_fp16.h>
#include <cstddef>
#include <cstdint>

#define SPI 9
#define BM  128

// Activations stored as fp16 (hi-only): per vertex [fp16 x C].
__device__ __align__(16) __half g_bufX[(size_t)8 * 50000 * 64]; // L0 out (32B/row) / L2 out (128B/row)
__device__ __align__(16) __half g_bufY[(size_t)8 * 50000 * 32]; // L1 out (64B/row)
// Weights pre-shuffled into mma.sync B-fragment order (single fp16 set):
__device__ __align__(16) uint4 g_WF1[9 * 1 * 2 * 32];
__device__ __align__(16) uint4 g_WF2[9 * 2 * 4 * 32];
__device__ __align__(16) uint4 g_WF3[9 * 4 * 8 * 32];

__device__ __forceinline__ void ffma2(float2 &d, const float2 &a, const float2 &b) {
    unsigned long long       &du = reinterpret_cast<unsigned long long &>(d);
    const unsigned long long &au = reinterpret_cast<const unsigned long long &>(a);
    const unsigned long long &bu = reinterpret_cast<const unsigned long long &>(b);
    asm("fma.rn.f32x2 %0, %1, %2, %0;" : "+l"(du) : "l"(au), "l"(bu));
}
__device__ __forceinline__ uint32_t smem_u32(const void *p) {
    uint32_t a;
    asm("{ .reg .u64 t; cvta.to.shared.u64 t, %1; cvt.u32.u64 %0, t; }" : "=r"(a) : "l"(p));
    return a;
}
#define SMEM_SWIZZLE_128B(o) ((o) ^ (((o) >> 3) & 0x70))

__device__ __forceinline__ void cp16(uint32_t dst, const void *src) {
    asm volatile("cp.async.cg.shared.global [%0], [%1], 16;" :: "r"(dst), "l"(src));
}
#define CP_COMMIT() asm volatile("cp.async.commit_group;" ::: "memory")
#define CP_WAIT1()  asm volatile("cp.async.wait_group 1;" ::: "memory")

__device__ __forceinline__ void ldmx4(uint32_t &r0, uint32_t &r1, uint32_t &r2,
                                      uint32_t &r3, uint32_t addr) {
    asm volatile("ldmatrix.sync.aligned.m8n8.x4.shared.b16 {%0,%1,%2,%3}, [%4];"
                 : "=r"(r0), "=r"(r1), "=r"(r2), "=r"(r3) : "r"(addr));
}
// fp16 inputs, fp32 accumulate
__device__ __forceinline__ void mma16816(float *c, const uint32_t *a,
                                         uint32_t b0, uint32_t b1) {
    asm volatile("mma.sync.aligned.m16n8k16.row.col.f32.f16.f16.f32 "
                 "{%0,%1,%2,%3}, {%4,%5,%6,%7}, {%8,%9}, {%0,%1,%2,%3};"
                 : "+f"(c[0]), "+f"(c[1]), "+f"(c[2]), "+f"(c[3])
                 : "r"(a[0]), "r"(a[1]), "r"(a[2]), "r"(a[3]), "r"(b0), "r"(b1));
}
__device__ __forceinline__ uint32_t pack_h2(float2 v) {
    __half2 hb = __float22half2_rn(v);
    return *(uint32_t *)&hb;
}

// ---------------------------------------------------------------------------
// Layer 0 (FFMA2): Cin=3 -> 16, writes fp16 rows (32B/vertex).
// ---------------------------------------------------------------------------
__global__ void layer0_kernel(const float *__restrict__ X, const int *__restrict__ idx,
                              const float *__restrict__ W, const float *__restrict__ bias,
                              __half *__restrict__ Y, int N) {
    __shared__ float Ws[27 * 16];
    __shared__ float bs[16];
    int tid = threadIdx.x;
    for (int t = tid; t < 27 * 16; t += blockDim.x) Ws[t] = W[t];
    if (tid < 16) bs[tid] = bias[tid];
    __syncthreads();

    int n = blockIdx.x * blockDim.x + tid;
    int b = blockIdx.y;
    if (n >= N) return;

    float2 acc[8];
#pragma unroll
    for (int j = 0; j < 8; j++) acc[j] = make_float2(bs[2 * j], bs[2 * j + 1]);

    const float *Xb = X + (size_t)b * N * 3;
#pragma unroll
    for (int s = 0; s < SPI; s++) {
        int r = idx[n * SPI + s];
        float xv[3];
        xv[0] = __ldg(Xb + (size_t)r * 3 + 0);
        xv[1] = __ldg(Xb + (size_t)r * 3 + 1);
        xv[2] = __ldg(Xb + (size_t)r * 3 + 2);
#pragma unroll
        for (int c = 0; c < 3; c++) {
            const float *wrow = Ws + (s * 3 + c) * 16;
            float2 vv = make_float2(xv[c], xv[c]);
#pragma unroll
            for (int j = 0; j < 8; j++) {
                float2 w = *(const float2 *)(wrow + 2 * j);
                ffma2(acc[j], vv, w);
            }
        }
    }
    uint32_t hw[8];
#pragma unroll
    for (int j = 0; j < 8; j++) hw[j] = pack_h2(acc[j]);
    char *y = (char *)Y + ((size_t)b * N + n) * 32;
    *(uint4 *)(y + 0)  = make_uint4(hw[0], hw[1], hw[2], hw[3]);
    *(uint4 *)(y + 16) = make_uint4(hw[4], hw[5], hw[6], hw[7]);
}

// ---------------------------------------------------------------------------
// Weight prep: W[S*CIN, COUT] -> mma B-fragment order, single fp16.
// ---------------------------------------------------------------------------
template <int CIN, int COUT>
__global__ void prep_wfrag(const float *__restrict__ W, uint4 *__restrict__ dst) {
    constexpr int KCH = CIN / 16, NGT = COUT / 16;
    constexpr int PER = KCH * NGT * 32;
    int s = blockIdx.x;
    for (int i = threadIdx.x; i < PER; i += blockDim.x) {
        int lane = i & 31, ngg = (i >> 5) % NGT, kc = (i >> 5) / NGT;
        int n0 = ngg * 16 + (lane >> 2);
        int kb = kc * 16 + 2 * (lane & 3);
        auto wsel = [&](int k, int n) -> uint32_t {
            float v = __ldg(W + (size_t)(s * CIN + k) * COUT + n);
            __half hb = __float2half_rn(v);
            return (uint32_t)(*(uint16_t *)&hb);
        };
        auto word = [&](int k, int n) { return wsel(k, n) | (wsel(k + 1, n) << 16); };
        uint4 q;
        q.x = word(kb,     n0);
        q.y = word(kb,     n0 + 8);
        q.z = word(kb + 8, n0);
        q.w = word(kb + 8, n0 + 8);
        dst[(size_t)s * PER + i] = q;
    }
}

// ---------------------------------------------------------------------------
// Unified spiral-conv layer: fp16 1-term mma.sync.
// SPG = 64/CIN spiral steps packed per 128B smem row; 3-deep cp.async pipe
// (always-commit keeps the wait_group 1 invariant through the tail).
// ---------------------------------------------------------------------------
template <int CIN, int COUT, bool FUSE>
__global__ void __launch_bounds__(256, 2)
layer_mma(const __half *__restrict__ X,
          const int   *__restrict__ idxg,
          const float *__restrict__ bias,
          const uint4 *__restrict__ WF,
          const float *__restrict__ Wf,
          const float *__restrict__ bf,
          void *__restrict__ Y,
          int N) {
    constexpr int KCH = CIN / 16;
    constexpr int NGT = COUT / 16;
    constexpr int WN  = (COUT >= 128) ? 2 : 1;
    constexpr int WM  = 8 / WN;
    constexpr int MT  = 128 / (WM * 16);
    constexpr int NG  = NGT / WN;
    constexpr int CB  = 2 * CIN;           // bytes per source row (fp16)
    constexpr int CPT = CB / 32;           // 16B chunks per thread (2 thr/row)
    constexpr int XROW = 2 * CIN;
    constexpr int SPG  = 64 / CIN;         // steps packed per stage
    constexpr int NSTG = (SPI + SPG - 1) / SPG;
    constexpr int IDXOFF = 65536;          // A stages: 3 x 16KB = 48KB < 65536
    constexpr int PRM = IDXOFF + 4608;
    constexpr int CSTR = 132;

    extern __shared__ __align__(1024) char smc[];
    uint32_t sb = smem_u32(smc);
    int tid = threadIdx.x, wid = tid >> 5, lane = tid & 31;
    int b = blockIdx.y, row0 = blockIdx.x * BM;
    int warpM = wid / WN, warpN = wid % WN;

    int *idxs = (int *)(smc + IDXOFF);
    for (int t = tid; t < SPI * BM; t += 256) {
        int m = t / SPI, s = t % SPI;
        int r = row0 + m;
        if (r >= N) r = N - 1;
        idxs[s * BM + m] = idxg[(size_t)r * SPI + s];
    }
    float *prm = (float *)(smc + PRM);
    if (FUSE) {
        for (int t = tid; t < 384; t += 256) prm[t] = Wf[t];
        if (tid < 3)    prm[384 + tid] = bf[tid];
        if (tid < COUT) prm[388 + tid] = bias[tid];
    } else {
        if (tid < COUT) prm[tid] = bias[tid];
    }

    float acc[MT][2 * NG][4];
#pragma unroll
    for (int mt = 0; mt < MT; mt++)
#pragma unroll
        for (int nf = 0; nf < 2 * NG; nf++)
#pragma unroll
            for (int c = 0; c < 4; c++) acc[mt][nf][c] = 0.0f;

    const char *Xb = (const char *)X + (size_t)b * N * XROW;
    int grow = tid >> 1, ghalf = tid & 1;
    uint32_t lm_row  = (uint32_t)(lane & 15);
    uint32_t lm_half = (uint32_t)(lane >> 4) << 4;

    __syncthreads();   // idxs ready

    // gather SPG steps' rows into packed segments of one 128B smem row
    auto issueA = [&](int stage) {
        int st = stage % 3;
        int s0 = stage * SPG;
        uint32_t ah = sb + (uint32_t)st * 16384;
#pragma unroll
        for (int j = 0; j < SPG; j++) {
            int s = s0 + j;
            if (s >= SPI) break;
            int r = idxs[s * BM + grow];
            const char *src = Xb + (size_t)r * XROW;
#pragma unroll
            for (int q = 0; q < CPT; q++) {
                int c16 = ghalf * CPT + q;
                uint32_t bo = (uint32_t)(grow * 128 + j * CB + 16 * c16);
                cp16(ah + SMEM_SWIZZLE_128B(bo), src + 16 * c16);
            }
        }
    };

    issueA(0);
    CP_COMMIT();
    if (NSTG > 1) issueA(1);
    CP_COMMIT();

    for (int stage = 0; stage < NSTG; stage++) {
        CP_WAIT1();            // oldest outstanding group (this stage) drained
        __syncthreads();
        if (stage + 2 < NSTG) issueA(stage + 2);
        CP_COMMIT();           // always commit: keeps group-count invariant
        uint32_t aH = sb + (uint32_t)(stage % 3) * 16384;
        int s0 = stage * SPG;
        int steps = SPI - s0; if (steps > SPG) steps = SPG;
        int kcmax = steps * KCH;               // full stage: 4
#pragma unroll
        for (int kc = 0; kc < SPG * KCH; kc++) {
            if (kc >= kcmax) break;
            int s_eff = s0 + kc / KCH;
            int kcw   = kc % KCH;
            uint32_t kcoff = (uint32_t)kc * 32 + lm_half;
            uint32_t Ah[MT][4];
#pragma unroll
            for (int mt = 0; mt < MT; mt++) {
                uint32_t ro = (uint32_t)(warpM * (16 * MT) + mt * 16 + lm_row) * 128 + kcoff;
                ldmx4(Ah[mt][0], Ah[mt][1], Ah[mt][2], Ah[mt][3],
                      aH + SMEM_SWIZZLE_128B(ro));
            }
#pragma unroll
            for (int ng = 0; ng < NG; ng++) {
                int ngg = warpN * NG + ng;
                const uint4 *bp = WF + (((size_t)s_eff * KCH + kcw) * NGT + ngg) * 32 + lane;
                uint4 q = __ldg(bp);
#pragma unroll
                for (int mt = 0; mt < MT; mt++) {
                    mma16816(acc[mt][2 * ng],     Ah[mt], q.x, q.z);
                    mma16816(acc[mt][2 * ng + 1], Ah[mt], q.y, q.w);
                }
            }
        }
    }

    if (!FUSE) {
        // write fp16 rows (+bias)
        char *Yb = (char *)Y + (size_t)b * N * (2 * COUT);
#pragma unroll
        for (int mt = 0; mt < MT; mt++) {
            int rr = row0 + warpM * (16 * MT) + mt * 16 + (lane >> 2);
#pragma unroll
            for (int nf = 0; nf < 2 * NG; nf++) {
                int c = warpN * (COUT / WN) + nf * 8 + (lane & 3) * 2;
                float bv0 = prm[c], bv1 = prm[c + 1];
                if (rr < N) {
                    uint32_t h = pack_h2(make_float2(acc[mt][nf][0] + bv0,
                                                     acc[mt][nf][1] + bv1));
                    *(uint32_t *)(Yb + (size_t)rr * (2 * COUT) + 2 * c) = h;
                }
                if (rr + 8 < N) {
                    uint32_t h = pack_h2(make_float2(acc[mt][nf][2] + bv0,
                                                     acc[mt][nf][3] + bv1));
                    *(uint32_t *)(Yb + (size_t)(rr + 8) * (2 * COUT) + 2 * c) = h;
                }
            }
        }
    } else {
        __syncthreads();
        float *Cs = (float *)smc;   // [128][CSTR] = 67584B; overlaps dead A+idx, not prm
#pragma unroll
        for (int mt = 0; mt < MT; mt++) {
            int r = warpM * (16 * MT) + mt * 16 + (lane >> 2);
#pragma unroll
            for (int nf = 0; nf < 2 * NG; nf++) {
                int c = warpN * (COUT / WN) + nf * 8 + (lane & 3) * 2;
                Cs[r * CSTR + c]           = acc[mt][nf][0] + prm[388 + c];
                Cs[r * CSTR + c + 1]       = acc[mt][nf][1] + prm[388 + c + 1];
                Cs[(r + 8) * CSTR + c]     = acc[mt][nf][2] + prm[388 + c];
                Cs[(r + 8) * CSTR + c + 1] = acc[mt][nf][3] + prm[388 + c + 1];
            }
        }
        __syncthreads();
        if (tid < BM) {
            int r = row0 + tid;
            float o0 = prm[384], o1 = prm[385], o2 = prm[386];
            const float *crow = Cs + tid * CSTR;
#pragma unroll 16
            for (int k = 0; k < COUT; k++) {
                float v = crow[k];
                o0 = fmaf(v, prm[3 * k + 0], o0);
                o1 = fmaf(v, prm[3 * k + 1], o1);
                o2 = fmaf(v, prm[3 * k + 2], o2);
            }
            if (r < N) {
                float *o = (float *)Y + ((size_t)b * N + r) * 3;
                o[0] = o0; o[1] = o1; o[2] = o2;
            }
        }
    }
}

// ---------------------------------------------------------------------------
extern "C" void kernel_launch(void *const *d_in, const int *in_sizes, int n_in,
                              void *d_out, int out_size) {
    const float *x   = (const float *)d_in[0];
    const int   *idx = (const int *)d_in[1];
    const float *W0  = (const float *)d_in[2];
    const float *b0  = (const float *)d_in[3];
    const float *W1  = (const float *)d_in[4];
    const float *b1  = (const float *)d_in[5];
    const float *W2  = (const float *)d_in[6];
    const float *b2  = (const float *)d_in[7];
    const float *W3  = (const float *)d_in[8];
    const float *b3  = (const float *)d_in[9];
    const float *Wf  = (const float *)d_in[10];
    const float *bf  = (const float *)d_in[11];
    float *out = (float *)d_out;

    int N = in_sizes[1] / SPI;
    int B = in_sizes[0] / (N * 3);

    __half *bufX, *bufY;
    cudaGetSymbolAddress((void **)&bufX, g_bufX);
    cudaGetSymbolAddress((void **)&bufY, g_bufY);
    uint4 *wf1, *wf2, *wf3;
    cudaGetSymbolAddress((void **)&wf1, g_WF1);
    cudaGetSymbolAddress((void **)&wf2, g_WF2);
    cudaGetSymbolAddress((void **)&wf3, g_WF3);

    constexpr int SMN1 = 65536 + 4608 + 32 * 4;
    constexpr int SMN2 = 65536 + 4608 + 64 * 4;
    constexpr int SMF  = 65536 + 4608 + (384 + 4 + 128) * 4;
    cudaFuncSetAttribute(layer_mma<16, 32, false>,
                         cudaFuncAttributeMaxDynamicSharedMemorySize, SMN1);
    cudaFuncSetAttribute(layer_mma<32, 64, false>,
                         cudaFuncAttributeMaxDynamicSharedMemorySize, SMN2);
    cudaFuncSetAttribute(layer_mma<64, 128, true>,
                         cudaFuncAttributeMaxDynamicSharedMemorySize, SMF);

    prep_wfrag<16, 32><<<9, 256>>>(W1, wf1);
    prep_wfrag<32, 64><<<9, 256>>>(W2, wf2);
    prep_wfrag<64, 128><<<9, 256>>>(W3, wf3);

    dim3 g0((N + 255) / 256, B);
    layer0_kernel<<<g0, 256>>>(x, idx, W0, b0, bufX, N);

    dim3 gl((N + BM - 1) / BM, B);
    layer_mma<16, 32, false><<<gl, 256, SMN1>>>(bufX, idx, b1, wf1,
                                                nullptr, nullptr, bufY, N);
    layer_mma<32, 64, false><<<gl, 256, SMN2>>>(bufY, idx, b2, wf2,
                                                nullptr, nullptr, bufX, N);
    layer_mma<64, 128, true><<<gl, 256, SMF>>>(bufX, idx, b3, wf3,
                                               Wf, bf, out, N);
}

// round 17
// speedup vs baseline: 4.1323x; 1.6478x over previous
#include <cuda_runtime.h>
#include <cuda_fp16.h>
#include <cstddef>
#include <cstdint>

#define SPI 9
#define BM  128

// Activations stored as fp16 (hi-only): per vertex [fp16 x C].
__device__ __align__(16) __half g_bufX[(size_t)8 * 50000 * 64]; // L0 out (32B/row) / L2 out (128B/row)
__device__ __align__(16) __half g_bufY[(size_t)8 * 50000 * 32]; // L1 out (64B/row)
// Weights pre-shuffled into mma.sync B-fragment order (single fp16 set):
__device__ __align__(16) uint4 g_WF1[9 * 1 * 2 * 32];
__device__ __align__(16) uint4 g_WF2[9 * 2 * 4 * 32];
// Folded layer3 weights: W3' = W3 @ Wf  [576, 3->8 padded], fragment order uint2
__device__ __align__(16) uint2 g_WF3f[9 * 4 * 32];
__device__ float g_b3f[3];   // b3 @ Wf + bf

__device__ __forceinline__ void ffma2(float2 &d, const float2 &a, const float2 &b) {
    unsigned long long       &du = reinterpret_cast<unsigned long long &>(d);
    const unsigned long long &au = reinterpret_cast<const unsigned long long &>(a);
    const unsigned long long &bu = reinterpret_cast<const unsigned long long &>(b);
    asm("fma.rn.f32x2 %0, %1, %2, %0;" : "+l"(du) : "l"(au), "l"(bu));
}
__device__ __forceinline__ uint32_t smem_u32(const void *p) {
    uint32_t a;
    asm("{ .reg .u64 t; cvta.to.shared.u64 t, %1; cvt.u32.u64 %0, t; }" : "=r"(a) : "l"(p));
    return a;
}
#define SMEM_SWIZZLE_128B(o) ((o) ^ (((o) >> 3) & 0x70))

__device__ __forceinline__ void cp16(uint32_t dst, const void *src) {
    asm volatile("cp.async.cg.shared.global [%0], [%1], 16;" :: "r"(dst), "l"(src));
}
#define CP_COMMIT() asm volatile("cp.async.commit_group;" ::: "memory")
#define CP_WAIT1()  asm volatile("cp.async.wait_group 1;" ::: "memory")

__device__ __forceinline__ void ldmx4(uint32_t &r0, uint32_t &r1, uint32_t &r2,
                                      uint32_t &r3, uint32_t addr) {
    asm volatile("ldmatrix.sync.aligned.m8n8.x4.shared.b16 {%0,%1,%2,%3}, [%4];"
                 : "=r"(r0), "=r"(r1), "=r"(r2), "=r"(r3) : "r"(addr));
}
// fp16 inputs, fp32 accumulate
__device__ __forceinline__ void mma16816(float *c, const uint32_t *a,
                                         uint32_t b0, uint32_t b1) {
    asm volatile("mma.sync.aligned.m16n8k16.row.col.f32.f16.f16.f32 "
                 "{%0,%1,%2,%3}, {%4,%5,%6,%7}, {%8,%9}, {%0,%1,%2,%3};"
                 : "+f"(c[0]), "+f"(c[1]), "+f"(c[2]), "+f"(c[3])
                 : "r"(a[0]), "r"(a[1]), "r"(a[2]), "r"(a[3]), "r"(b0), "r"(b1));
}
__device__ __forceinline__ uint32_t pack_h2(float2 v) {
    __half2 hb = __float22half2_rn(v);
    return *(uint32_t *)&hb;
}
__device__ __forceinline__ uint32_t pack_hh(float a, float b) {
    return pack_h2(make_float2(a, b));
}

// ---------------------------------------------------------------------------
// Layer 0 (FFMA2): Cin=3 -> 16, writes fp16 rows (32B/vertex).
// ---------------------------------------------------------------------------
__global__ void layer0_kernel(const float *__restrict__ X, const int *__restrict__ idx,
                              const float *__restrict__ W, const float *__restrict__ bias,
                              __half *__restrict__ Y, int N) {
    __shared__ float Ws[27 * 16];
    __shared__ float bs[16];
    int tid = threadIdx.x;
    for (int t = tid; t < 27 * 16; t += blockDim.x) Ws[t] = W[t];
    if (tid < 16) bs[tid] = bias[tid];
    __syncthreads();

    int n = blockIdx.x * blockDim.x + tid;
    int b = blockIdx.y;
    if (n >= N) return;

    float2 acc[8];
#pragma unroll
    for (int j = 0; j < 8; j++) acc[j] = make_float2(bs[2 * j], bs[2 * j + 1]);

    const float *Xb = X + (size_t)b * N * 3;
#pragma unroll
    for (int s = 0; s < SPI; s++) {
        int r = idx[n * SPI + s];
        float xv[3];
        xv[0] = __ldg(Xb + (size_t)r * 3 + 0);
        xv[1] = __ldg(Xb + (size_t)r * 3 + 1);
        xv[2] = __ldg(Xb + (size_t)r * 3 + 2);
#pragma unroll
        for (int c = 0; c < 3; c++) {
            const float *wrow = Ws + (s * 3 + c) * 16;
            float2 vv = make_float2(xv[c], xv[c]);
#pragma unroll
            for (int j = 0; j < 8; j++) {
                float2 w = *(const float2 *)(wrow + 2 * j);
                ffma2(acc[j], vv, w);
            }
        }
    }
    uint32_t hw[8];
#pragma unroll
    for (int j = 0; j < 8; j++) hw[j] = pack_h2(acc[j]);
    char *y = (char *)Y + ((size_t)b * N + n) * 32;
    *(uint4 *)(y + 0)  = make_uint4(hw[0], hw[1], hw[2], hw[3]);
    *(uint4 *)(y + 16) = make_uint4(hw[4], hw[5], hw[6], hw[7]);
}

// ---------------------------------------------------------------------------
// Weight prep: W[S*CIN, COUT] -> mma B-fragment order, single fp16.
// ---------------------------------------------------------------------------
template <int CIN, int COUT>
__global__ void prep_wfrag(const float *__restrict__ W, uint4 *__restrict__ dst) {
    constexpr int KCH = CIN / 16, NGT = COUT / 16;
    constexpr int PER = KCH * NGT * 32;
    int s = blockIdx.x;
    for (int i = threadIdx.x; i < PER; i += blockDim.x) {
        int lane = i & 31, ngg = (i >> 5) % NGT, kc = (i >> 5) / NGT;
        int n0 = ngg * 16 + (lane >> 2);
        int kb = kc * 16 + 2 * (lane & 3);
        auto wsel = [&](int k, int n) -> uint32_t {
            float v = __ldg(W + (size_t)(s * CIN + k) * COUT + n);
            __half hb = __float2half_rn(v);
            return (uint32_t)(*(uint16_t *)&hb);
        };
        auto word = [&](int k, int n) { return wsel(k, n) | (wsel(k + 1, n) << 16); };
        uint4 q;
        q.x = word(kb,     n0);
        q.y = word(kb,     n0 + 8);
        q.z = word(kb + 8, n0);
        q.w = word(kb + 8, n0 + 8);
        dst[(size_t)s * PER + i] = q;
    }
}

// ---------------------------------------------------------------------------
// Folded layer3 weight prep: W3' = W3 @ Wf (fp32 dot, fp16 round), fragment
// order for n=8 mma tile (cols 3..7 zero). Also b3' = b3 @ Wf + bf.
// ---------------------------------------------------------------------------
__global__ void prep_w3f(const float *__restrict__ W3, const float *__restrict__ Wf,
                         const float *__restrict__ b3, const float *__restrict__ bf,
                         uint2 *__restrict__ dst) {
    int s = blockIdx.x;           // 0..8
    int i = threadIdx.x;          // 0..127 = kc*32 + lane
    int kc = i >> 5, lane = i & 31;
    int n0 = lane >> 2;           // 0..7
    int kb = kc * 16 + 2 * (lane & 3);
    auto wval = [&](int k) -> float {        // W3'[s*64+k][n0]
        if (n0 >= 3) return 0.0f;
        float sum = 0.0f;
        const float *row = W3 + (size_t)(s * 64 + k) * 128;
        for (int j = 0; j < 128; j++) sum += row[j] * Wf[j * 3 + n0];
        return sum;
    };
    auto word = [&](int k) -> uint32_t { return pack_hh(wval(k), wval(k + 1)); };
    dst[s * 128 + i] = make_uint2(word(kb), word(kb + 8));
    if (s == 0 && i < 3) {
        float sum = bf[i];
        for (int j = 0; j < 128; j++) sum += b3[j] * Wf[j * 3 + i];
        g_b3f[i] = sum;
    }
}

// ---------------------------------------------------------------------------
// Layers 1-2: fp16 1-term mma.sync; SPG steps packed per 128B row; 3-deep
// cp.async pipeline. Compact smem (stages at 0..48K, idx at 48K).
// ---------------------------------------------------------------------------
template <int CIN, int COUT, int OCC>
__global__ void __launch_bounds__(256, OCC)
layer_mma(const __half *__restrict__ X,
          const int   *__restrict__ idxg,
          const float *__restrict__ bias,
          const uint4 *__restrict__ WF,
          void *__restrict__ Y,
          int N) {
    constexpr int KCH = CIN / 16;
    constexpr int NGT = COUT / 16;
    constexpr int NG  = NGT;
    constexpr int CB  = 2 * CIN;
    constexpr int CPT = CB / 32;
    constexpr int XROW = 2 * CIN;
    constexpr int SPG  = 64 / CIN;
    constexpr int NSTG = (SPI + SPG - 1) / SPG;
    constexpr int IDXOFF = 49152;          // 3 stages x 16KB
    constexpr int PRM = IDXOFF + 4608;

    extern __shared__ __align__(1024) char smc[];
    uint32_t sb = smem_u32(smc);
    int tid = threadIdx.x, wid = tid >> 5, lane = tid & 31;
    int b = blockIdx.y, row0 = blockIdx.x * BM;
    int warpM = wid;

    int *idxs = (int *)(smc + IDXOFF);
    for (int t = tid; t < SPI * BM; t += 256) {
        int m = t / SPI, s = t % SPI;
        int r = row0 + m;
        if (r >= N) r = N - 1;
        idxs[s * BM + m] = idxg[(size_t)r * SPI + s];
    }
    float *prm = (float *)(smc + PRM);
    if (tid < COUT) prm[tid] = bias[tid];

    float acc[2 * NG][4];
#pragma unroll
    for (int nf = 0; nf < 2 * NG; nf++)
#pragma unroll
        for (int c = 0; c < 4; c++) acc[nf][c] = 0.0f;

    const char *Xb = (const char *)X + (size_t)b * N * XROW;
    int grow = tid >> 1, ghalf = tid & 1;
    uint32_t lm_row  = (uint32_t)(lane & 15);
    uint32_t lm_half = (uint32_t)(lane >> 4) << 4;

    __syncthreads();   // idxs ready

    auto issueA = [&](int stage) {
        int st = stage % 3;
        int s0 = stage * SPG;
        uint32_t ah = sb + (uint32_t)st * 16384;
#pragma unroll
        for (int j = 0; j < SPG; j++) {
            int s = s0 + j;
            if (s >= SPI) break;
            int r = idxs[s * BM + grow];
            const char *src = Xb + (size_t)r * XROW;
#pragma unroll
            for (int q = 0; q < CPT; q++) {
                int c16 = ghalf * CPT + q;
                uint32_t bo = (uint32_t)(grow * 128 + j * CB + 16 * c16);
                cp16(ah + SMEM_SWIZZLE_128B(bo), src + 16 * c16);
            }
        }
    };

    issueA(0);
    CP_COMMIT();
    if (NSTG > 1) issueA(1);
    CP_COMMIT();

    for (int stage = 0; stage < NSTG; stage++) {
        CP_WAIT1();
        __syncthreads();
        if (stage + 2 < NSTG) issueA(stage + 2);
        CP_COMMIT();
        uint32_t aH = sb + (uint32_t)(stage % 3) * 16384;
        int s0 = stage * SPG;
        int steps = SPI - s0; if (steps > SPG) steps = SPG;
        int kcmax = steps * KCH;
#pragma unroll
        for (int kc = 0; kc < SPG * KCH; kc++) {
            if (kc >= kcmax) break;
            int s_eff = s0 + kc / KCH;
            int kcw   = kc % KCH;
            uint32_t kcoff = (uint32_t)kc * 32 + lm_half;
            uint32_t Ah[4];
            {
                uint32_t ro = (uint32_t)(warpM * 16 + lm_row) * 128 + kcoff;
                ldmx4(Ah[0], Ah[1], Ah[2], Ah[3], aH + SMEM_SWIZZLE_128B(ro));
            }
#pragma unroll
            for (int ng = 0; ng < NG; ng++) {
                const uint4 *bp = WF + (((size_t)s_eff * KCH + kcw) * NGT + ng) * 32 + lane;
                uint4 q = __ldg(bp);
                mma16816(acc[2 * ng],     Ah, q.x, q.z);
                mma16816(acc[2 * ng + 1], Ah, q.y, q.w);
            }
        }
    }

    // write fp16 rows (+bias)
    char *Yb = (char *)Y + (size_t)b * N * (2 * COUT);
    {
        int rr = row0 + warpM * 16 + (lane >> 2);
#pragma unroll
        for (int nf = 0; nf < 2 * NG; nf++) {
            int c = nf * 8 + (lane & 3) * 2;
            float bv0 = prm[c], bv1 = prm[c + 1];
            if (rr < N) {
                uint32_t h = pack_hh(acc[nf][0] + bv0, acc[nf][1] + bv1);
                *(uint32_t *)(Yb + (size_t)rr * (2 * COUT) + 2 * c) = h;
            }
            if (rr + 8 < N) {
                uint32_t h = pack_hh(acc[nf][2] + bv0, acc[nf][3] + bv1);
                *(uint32_t *)(Yb + (size_t)(rr + 8) * (2 * COUT) + 2 * c) = h;
            }
        }
    }
}

// ---------------------------------------------------------------------------
// Layer 3 FUSED with final linear: gather-GEMM, K=576, N=8 (3 live cols).
// 8 warps x 16 rows; per k-chunk: 1 ldmatrix + 1 LDG.64 + 1 mma.
// ---------------------------------------------------------------------------
__global__ void __launch_bounds__(256, 4)
layer3_fused(const __half *__restrict__ X,      // [B,N,64] fp16
             const int   *__restrict__ idxg,
             const uint2 *__restrict__ WFf,     // folded fragments
             float *__restrict__ out,           // [B,N,3]
             int N) {
    constexpr int IDXOFF = 49152;
    extern __shared__ __align__(1024) char smc[];
    uint32_t sb = smem_u32(smc);
    int tid = threadIdx.x, wid = tid >> 5, lane = tid & 31;
    int b = blockIdx.y, row0 = blockIdx.x * BM;

    int *idxs = (int *)(smc + IDXOFF);
    for (int t = tid; t < SPI * BM; t += 256) {
        int m = t / SPI, s = t % SPI;
        int r = row0 + m;
        if (r >= N) r = N - 1;
        idxs[s * BM + m] = idxg[(size_t)r * SPI + s];
    }

    float acc[4] = {0.0f, 0.0f, 0.0f, 0.0f};

    const char *Xb = (const char *)X + (size_t)b * N * 128;
    int grow = tid >> 1, ghalf = tid & 1;
    uint32_t lm_row  = (uint32_t)(lane & 15);
    uint32_t lm_half = (uint32_t)(lane >> 4) << 4;

    __syncthreads();

    auto issueA = [&](int s) {
        int st = s % 3;
        int r = idxs[s * BM + grow];
        const char *src = Xb + (size_t)r * 128;
        uint32_t ah = sb + (uint32_t)st * 16384;
#pragma unroll
        for (int q = 0; q < 4; q++) {
            int c16 = ghalf * 4 + q;
            uint32_t bo = (uint32_t)(grow * 128 + 16 * c16);
            cp16(ah + SMEM_SWIZZLE_128B(bo), src + 16 * c16);
        }
    };

    issueA(0);
    CP_COMMIT();
    issueA(1);
    CP_COMMIT();

    for (int s = 0; s < SPI; s++) {
        CP_WAIT1();
        __syncthreads();
        if (s + 2 < SPI) issueA(s + 2);
        CP_COMMIT();
        uint32_t aH = sb + (uint32_t)(s % 3) * 16384;
#pragma unroll
        for (int kc = 0; kc < 4; kc++) {
            uint32_t ro = (uint32_t)(wid * 16 + lm_row) * 128 + kc * 32 + lm_half;
            uint32_t Ah[4];
            ldmx4(Ah[0], Ah[1], Ah[2], Ah[3], aH + SMEM_SWIZZLE_128B(ro));
            uint2 q = __ldg(WFf + ((size_t)s * 4 + kc) * 32 + lane);
            mma16816(acc, Ah, q.x, q.y);
        }
    }

    // epilogue: cols (lane&3)*2, +1 ; rows wid*16 + (lane>>2), +8
    int c0 = (lane & 3) * 2;
    int r0 = row0 + wid * 16 + (lane >> 2);
    int r1 = r0 + 8;
    if (c0 < 3) {
        if (r0 < N) {
            float *o = out + ((size_t)b * N + r0) * 3 + c0;
            o[0] = acc[0] + g_b3f[c0];
            if (c0 + 1 < 3) o[1] = acc[1] + g_b3f[c0 + 1];
        }
        if (r1 < N) {
            float *o = out + ((size_t)b * N + r1) * 3 + c0;
            o[0] = acc[2] + g_b3f[c0];
            if (c0 + 1 < 3) o[1] = acc[3] + g_b3f[c0 + 1];
        }
    }
}

// ---------------------------------------------------------------------------
extern "C" void kernel_launch(void *const *d_in, const int *in_sizes, int n_in,
                              void *d_out, int out_size) {
    const float *x   = (const float *)d_in[0];
    const int   *idx = (const int *)d_in[1];
    const float *W0  = (const float *)d_in[2];
    const float *b0  = (const float *)d_in[3];
    const float *W1  = (const float *)d_in[4];
    const float *b1  = (const float *)d_in[5];
    const float *W2  = (const float *)d_in[6];
    const float *b2  = (const float *)d_in[7];
    const float *W3  = (const float *)d_in[8];
    const float *b3  = (const float *)d_in[9];
    const float *Wf  = (const float *)d_in[10];
    const float *bf  = (const float *)d_in[11];
    float *out = (float *)d_out;

    int N = in_sizes[1] / SPI;
    int B = in_sizes[0] / (N * 3);

    __half *bufX, *bufY;
    cudaGetSymbolAddress((void **)&bufX, g_bufX);
    cudaGetSymbolAddress((void **)&bufY, g_bufY);
    uint4 *wf1, *wf2;
    uint2 *wf3f;
    cudaGetSymbolAddress((void **)&wf1, g_WF1);
    cudaGetSymbolAddress((void **)&wf2, g_WF2);
    cudaGetSymbolAddress((void **)&wf3f, g_WF3f);

    constexpr int SMN1 = 49152 + 4608 + 32 * 4;
    constexpr int SMN2 = 49152 + 4608 + 64 * 4;
    constexpr int SMF  = 49152 + 4608;
    cudaFuncSetAttribute(layer_mma<16, 32, 4>,
                         cudaFuncAttributeMaxDynamicSharedMemorySize, SMN1);
    cudaFuncSetAttribute(layer_mma<32, 64, 3>,
                         cudaFuncAttributeMaxDynamicSharedMemorySize, SMN2);
    cudaFuncSetAttribute(layer3_fused,
                         cudaFuncAttributeMaxDynamicSharedMemorySize, SMF);

    prep_wfrag<16, 32><<<9, 256>>>(W1, wf1);
    prep_wfrag<32, 64><<<9, 256>>>(W2, wf2);
    prep_w3f<<<9, 128>>>(W3, Wf, b3, bf, wf3f);

    dim3 g0((N + 255) / 256, B);
    layer0_kernel<<<g0, 256>>>(x, idx, W0, b0, bufX, N);

    dim3 gl((N + BM - 1) / BM, B);
    layer_mma<16, 32, 4><<<gl, 256, SMN1>>>(bufX, idx, b1, wf1, bufY, N);
    layer_mma<32, 64, 3><<<gl, 256, SMN2>>>(bufY, idx, b2, wf2, bufX, N);
    layer3_fused<<<gl, 256, SMF>>>(bufX, idx, wf3f, out, N);
}